// round 13
// baseline (speedup 1.0000x reference)
#include <cuda_runtime.h>
#include <math.h>
#include <stdint.h>

// ---------------- problem constants ----------------
#define BB   128
#define NN   128
#define FDIM 13
#define DD   256
#define HH   8
#define LL   8
#define KKN  10
#define FFN  512
#define TOK  (BB*NN)       // 16384
#define ROWS2 (TOK*KKN)    // 163840

// ---------------- scratch (device globals; no allocations allowed) ----------
__device__ float gScale[BB*DD];
__device__ float gShift[BB*DD];
__device__ float gEnc [TOK*DD];
__device__ float gLf  [TOK*DD];
__device__ float gXbuf[TOK*DD];
__device__ float gSkip[TOK*DD];
__device__ float gBufFF[TOK*FFN];
__device__ float gTmp [TOK*DD];
__device__ float gQKV [TOK*3*DD];
__device__ float gAtt [TOK*DD];
__device__ float gLocal[(size_t)ROWS2*FFN];   // 335 MB
__device__ float gHid  [(size_t)ROWS2*FFN];   // 335 MB
__device__ float gOut2 [(size_t)ROWS2*DD];    // 168 MB
__device__ float gW1p  [32*FFN];
__device__ int   gIdx  [TOK*KKN];

// ---------------- math helpers ----------------
__device__ __forceinline__ float geluf(float x){
    float x3 = x*x*x;
    return 0.5f*x*(1.f + tanhf(0.7978845608028654f*(x + 0.044715f*x3)));
}
__device__ __forceinline__ float siluf(float x){
    return x / (1.f + expf(-x));
}
__device__ __forceinline__ float blockReduce256(float v, float* scr){
    #pragma unroll
    for (int o=16;o;o>>=1) v += __shfl_xor_sync(0xffffffffu, v, o);
    if ((threadIdx.x & 31) == 0) scr[threadIdx.x>>5] = v;
    __syncthreads();
    if (threadIdx.x < 32){
        float x = (threadIdx.x < 8) ? scr[threadIdx.x] : 0.f;
        #pragma unroll
        for (int o=4;o;o>>=1) x += __shfl_xor_sync(0xffffffffu, x, o);
        if (threadIdx.x == 0) scr[0] = x;
    }
    __syncthreads();
    float r = scr[0];
    __syncthreads();
    return r;
}

// ---------------- tiled SGEMM: C = A(MxK) @ B(KxN) + bias, optional GELU ----
// Requires M%128==0, N%128==0, K%8==0 (true for all call sites).
#define GBM 128
#define GBN 128
#define GBK 8
template<int EPI>
__global__ void __launch_bounds__(256) sgemm_kernel(int M, int N, int K,
        const float* __restrict__ A, const float* __restrict__ B,
        const float* __restrict__ bias, float* __restrict__ C){
    __shared__ float As[GBK][GBM];
    __shared__ float Bs[GBK][GBN];
    int tid = threadIdx.x;
    int br = blockIdx.y, bc = blockIdx.x;
    const float* Ag = A + (size_t)br*GBM*K;
    const float* Bg = B + bc*GBN;
    float* Cg = C + (size_t)br*GBM*N + bc*GBN;
    int aRow = tid >> 1, aCol = (tid & 1) << 2;
    int bRow = tid >> 5, bCol = (tid & 31) << 2;
    int tr = (tid >> 4) << 3, tc = (tid & 15) << 3;
    float acc[8][8] = {};
    for (int k0 = 0; k0 < K; k0 += GBK){
        float4 a4 = *reinterpret_cast<const float4*>(Ag + (size_t)aRow*K + aCol);
        As[aCol+0][aRow]=a4.x; As[aCol+1][aRow]=a4.y;
        As[aCol+2][aRow]=a4.z; As[aCol+3][aRow]=a4.w;
        float4 b4 = *reinterpret_cast<const float4*>(Bg + (size_t)bRow*N + bCol);
        *reinterpret_cast<float4*>(&Bs[bRow][bCol]) = b4;
        __syncthreads();
        Ag += GBK; Bg += (size_t)GBK*N;
        #pragma unroll
        for (int k=0;k<GBK;k++){
            float4 m0 = *reinterpret_cast<const float4*>(&As[k][tr]);
            float4 m1 = *reinterpret_cast<const float4*>(&As[k][tr+4]);
            float4 n0 = *reinterpret_cast<const float4*>(&Bs[k][tc]);
            float4 n1 = *reinterpret_cast<const float4*>(&Bs[k][tc+4]);
            float rm[8]={m0.x,m0.y,m0.z,m0.w,m1.x,m1.y,m1.z,m1.w};
            float rn[8]={n0.x,n0.y,n0.z,n0.w,n1.x,n1.y,n1.z,n1.w};
            #pragma unroll
            for (int i=0;i<8;i++)
                #pragma unroll
                for (int j=0;j<8;j++) acc[i][j] += rm[i]*rn[j];
        }
        __syncthreads();
    }
    #pragma unroll
    for (int i=0;i<8;i++){
        float* crow = Cg + (size_t)(tr+i)*N + tc;
        #pragma unroll
        for (int j=0;j<8;j+=4){
            float4 v;
            v.x = acc[i][j+0] + bias[bc*GBN + tc + j + 0];
            v.y = acc[i][j+1] + bias[bc*GBN + tc + j + 1];
            v.z = acc[i][j+2] + bias[bc*GBN + tc + j + 2];
            v.w = acc[i][j+3] + bias[bc*GBN + tc + j + 3];
            if (EPI == 1){ v.x=geluf(v.x); v.y=geluf(v.y); v.z=geluf(v.z); v.w=geluf(v.w); }
            *reinterpret_cast<float4*>(crow + j) = v;
        }
    }
}

// ---------------- time embedding (per batch) ----------------
__global__ void time_kernel(const float* __restrict__ tin,
        const float* __restrict__ fw1, const float* __restrict__ fw2,
        const float* __restrict__ tw, float* __restrict__ scale,
        float* __restrict__ shift){
    __shared__ float e[256];
    __shared__ float hbuf[512];
    __shared__ float tb[256];
    int b = blockIdx.x, tid = threadIdx.x;  // 256 threads
    float t = tin[b];
    if (tid < 128){
        float emb = 9.210340371976184f / 127.f;   // log(1e4)/(half-1)
        float fr = expf(-emb * (float)tid);
        float ang = t * fr * 1000.f;
        e[tid]      = sinf(ang);
        e[tid+128]  = cosf(ang);
    }
    __syncthreads();
    for (int jj = tid; jj < 512; jj += 256){
        float a = 0.f;
        for (int i=0;i<256;i++) a += e[i]*fw1[i*512+jj];
        hbuf[jj] = siluf(a);
    }
    __syncthreads();
    {
        float a = 0.f;
        for (int i=0;i<512;i++) a += hbuf[i]*fw2[i*256+tid];
        tb[tid] = siluf(a);
    }
    __syncthreads();
    for (int jj = tid; jj < 512; jj += 256){
        float a = 0.f;
        for (int i=0;i<256;i++) a += tb[i]*tw[i*512+jj];
        if (jj < 256) scale[b*256+jj] = a;
        else          shift[b*256+jj-256] = a;
    }
}

// ---------------- encoder layer 1 (K=13, fused gelu) ----------------
__global__ void enc1_kernel(const float* __restrict__ feats,
        const float* __restrict__ w1, const float* __restrict__ b1,
        float* __restrict__ outp){
    __shared__ float f[FDIM];
    int bn = blockIdx.x, j = threadIdx.x; // 512 threads
    if (j < FDIM) f[j] = feats[(size_t)bn*FDIM + j];
    __syncthreads();
    float acc = b1[j];
    #pragma unroll
    for (int i=0;i<FDIM;i++) acc += f[i]*w1[i*512+j];
    outp[(size_t)bn*512 + j] = geluf(acc);
}

// ---------------- modulation: enc = enc*(1+m*scale)+m*shift ----------------
__global__ void mod_kernel(float* enc, const float* __restrict__ mask,
        const float* __restrict__ sc, const float* __restrict__ sh){
    int idx = blockIdx.x*blockDim.x + threadIdx.x;
    if (idx >= TOK*DD) return;
    int c = idx & 255, bn = idx >> 8, b = bn >> 7;
    float m = mask[bn];
    enc[idx] = enc[idx]*(1.f + m*sc[b*256+c]) + m*sh[b*256+c];
}

// ---------------- KNN (per batch block, 128 threads, thread=m) --------------
template<int DIM>
__global__ void knn_kernel(const float* __restrict__ pts,
        const float* __restrict__ mask, int* __restrict__ idxout){
    constexpr int P = (DIM == 2) ? 2 : (DIM + 1);
    extern __shared__ float sm[];
    float* qs = sm;                  // 128*P
    float* rs = qs + 128*P;          // 128
    float* wv = rs + 128;            // 4
    int*   wi = (int*)(wv + 4);      // 4
    int*   win = wi + 4;             // 1
    int b = blockIdx.x, tid = threadIdx.x;
    for (int t = tid; t < 128*DIM; t += 128){
        int m = t / DIM, i = t - m*DIM;
        qs[m*P+i] = pts[(size_t)(b*128+m)*DIM + i] + 999.f*(1.f - mask[b*128+m]);
    }
    __syncthreads();
    {
        float s = 0.f;
        for (int i=0;i<DIM;i++){ float v = qs[tid*P+i]; s += v*v; }
        rs[tid] = s;
    }
    __syncthreads();
    for (int n=0;n<128;n++){
        float dot = 0.f;
        for (int i=0;i<DIM;i++) dot += qs[n*P+i]*qs[tid*P+i];
        float myd = (rs[n] - 2.f*dot) + rs[tid];
        for (int rsel=0; rsel<KKN+1; rsel++){
            float v = myd; int ii = tid;
            #pragma unroll
            for (int off=16; off; off>>=1){
                float ov = __shfl_down_sync(0xffffffffu, v, off);
                int   oi = __shfl_down_sync(0xffffffffu, ii, off);
                if (ov < v || (ov == v && oi < ii)){ v = ov; ii = oi; }
            }
            if ((tid & 31) == 0){ wv[tid>>5] = v; wi[tid>>5] = ii; }
            __syncthreads();
            if (tid == 0){
                float bv = wv[0]; int bi = wi[0];
                #pragma unroll
                for (int w=1; w<4; w++)
                    if (wv[w] < bv || (wv[w]==bv && wi[w]<bi)){ bv=wv[w]; bi=wi[w]; }
                *win = bi;
                if (rsel >= 1) idxout[(size_t)(b*128+n)*KKN + (rsel-1)] = bi;
            }
            __syncthreads();
            if (tid == *win) myd = 3.0e38f;
        }
        __syncthreads();
    }
}

// ---------------- gathers for neighbor MLPs ----------------
__global__ void gather1_kernel(const float* __restrict__ feats,
        const int* __restrict__ idx, float* __restrict__ outp){
    int i = blockIdx.x*blockDim.x + threadIdx.x;
    if (i >= ROWS2*32) return;
    int r = i >> 5, c = i & 31;
    int bn = r / KKN, k = r - bn*KKN;
    int b = bn >> 7;
    float v = 0.f;
    if (c < 13){
        int nb = idx[bn*KKN + k];
        v = feats[(size_t)(b*128+nb)*FDIM + c] - feats[(size_t)bn*FDIM + c];
    } else if (c < 26){
        v = feats[(size_t)bn*FDIM + (c-13)];
    }
    outp[i] = v;
}
__global__ void gather2_kernel(const float* __restrict__ lf,
        const int* __restrict__ idx, float* __restrict__ outp){
    size_t i = (size_t)blockIdx.x*blockDim.x + threadIdx.x;
    if (i >= (size_t)ROWS2*512) return;
    int r = (int)(i >> 9), c = (int)(i & 511);
    int bn = r / KKN, k = r - bn*KKN;
    int b = bn >> 7;
    float v;
    if (c < 256){
        int nb = idx[bn*KKN + k];
        v = lf[(size_t)(b*128+nb)*256 + c] - lf[(size_t)bn*256 + c];
    } else {
        v = lf[(size_t)bn*256 + (c-256)];
    }
    outp[i] = v;
}
__global__ void padw1_kernel(const float* __restrict__ w1, float* __restrict__ wp){
    int i = blockIdx.x*blockDim.x + threadIdx.x;
    if (i >= 32*512) return;
    int row = i >> 9, col = i & 511;
    wp[i] = (row < 26) ? w1[row*512 + col] : 0.f;
}

// ---------------- mean over K (optionally add enc, dual write) -------------
__global__ void reduce_mean_kernel(const float* __restrict__ in,
        const float* __restrict__ addsrc, float* __restrict__ out,
        float* __restrict__ out2){
    int idx = blockIdx.x*blockDim.x + threadIdx.x;
    if (idx >= TOK*DD) return;
    int bn = idx >> 8, c = idx & 255;
    const float* p = in + ((size_t)bn*KKN)*256 + c;
    float s = 0.f;
    #pragma unroll
    for (int k=0;k<KKN;k++) s += p[(size_t)k*256];
    s *= (1.f/KKN);
    if (addsrc){
        float v = addsrc[idx] + s;
        out[idx] = v;
        out2[idx] = v;
    } else {
        out[idx] = s;
    }
}

// ---------------- attention (per (b,h) block; two-pass softmax) -------------
__global__ void __launch_bounds__(128) attn_kernel(const float* __restrict__ qkv,
        const float* __restrict__ mask, float* __restrict__ outp){
    __shared__ float Ks[128*32];
    __shared__ float Vs[128*32];
    __shared__ float Ms[128];
    int b = blockIdx.x >> 3, h = blockIdx.x & 7;
    int tid = threadIdx.x; // 128
    const float* base = qkv + (size_t)b*128*768;
    for (int t = tid; t < 128*8; t += 128){
        int m = t >> 3, dq = (t & 7) << 2;
        *reinterpret_cast<float4*>(&Ks[m*32+dq]) =
            *reinterpret_cast<const float4*>(&base[(size_t)m*768 + 256 + h*32 + dq]);
        *reinterpret_cast<float4*>(&Vs[m*32+dq]) =
            *reinterpret_cast<const float4*>(&base[(size_t)m*768 + 512 + h*32 + dq]);
    }
    Ms[tid] = mask[b*128+tid];
    float q[32];
    #pragma unroll
    for (int d=0; d<32; d+=4)
        *reinterpret_cast<float4*>(&q[d]) =
            *reinterpret_cast<const float4*>(&base[(size_t)tid*768 + h*32 + d]);
    __syncthreads();
    const float scl = 0.17677669529663687f; // 1/sqrt(32)
    float mx = -1e30f;
    for (int m=0;m<128;m++){
        float s = 0.f;
        #pragma unroll
        for (int d=0; d<32; d++) s += q[d]*Ks[m*32+d];
        s = (Ms[m] > 0.f) ? s*scl : -1e9f;
        mx = fmaxf(mx, s);
    }
    float sum = 0.f;
    float acc[32] = {};
    for (int m=0;m<128;m++){
        float s = 0.f;
        #pragma unroll
        for (int d=0; d<32; d++) s += q[d]*Ks[m*32+d];
        s = (Ms[m] > 0.f) ? s*scl : -1e9f;
        float e = expf(s - mx);
        sum += e;
        #pragma unroll
        for (int d=0; d<32; d++) acc[d] += e*Vs[m*32+d];
    }
    float inv = 1.f/sum;
    float* o = outp + (size_t)(b*128+tid)*256 + h*32;
    #pragma unroll
    for (int d=0; d<32; d+=4){
        float4 v; v.x=acc[d]*inv; v.y=acc[d+1]*inv; v.z=acc[d+2]*inv; v.w=acc[d+3]*inv;
        *reinterpret_cast<float4*>(o + d) = v;
    }
}

// ---------------- residual + LayerNorm (optional gamma*mask on t) -----------
__global__ void ln_kernel(const float* res, const float* t,
        const float* __restrict__ g, const float* __restrict__ bb,
        const float* __restrict__ gamma, const float* __restrict__ mask,
        float* outp){
    __shared__ float scr[8];
    int bn = blockIdx.x, c = threadIdx.x; // 256 threads
    size_t off = (size_t)bn*256 + c;
    float hv = t[off];
    if (gamma) hv *= gamma[c] * mask[bn];
    float v = res[off] + hv;
    float mean = blockReduce256(v, scr) * (1.f/256.f);
    float d = v - mean;
    float var = blockReduce256(d*d, scr) * (1.f/256.f);
    outp[off] = d * rsqrtf(var + 1e-5f) * g[c] + bb[c];
}

// ---------------- final add ----------------
__global__ void add_kernel(const float* __restrict__ a, const float* __restrict__ b,
        float* __restrict__ o){
    int idx = blockIdx.x*blockDim.x + threadIdx.x;
    if (idx >= TOK*DD) return;
    o[idx] = a[idx] + b[idx];
}

// ---------------- host ----------------
static void gemm_launch(int M, int N, int K, const float* A, const float* B,
                        const float* bias, float* C, bool ge){
    dim3 grid(N/128, M/128);
    if (ge) sgemm_kernel<1><<<grid, 256>>>(M, N, K, A, B, bias, C);
    else    sgemm_kernel<0><<<grid, 256>>>(M, N, K, A, B, bias, C);
}

extern "C" void kernel_launch(void* const* d_in, const int* in_sizes, int n_in,
                              void* d_out, int out_size){
    const float* in_feat   = (const float*)d_in[0];
    const float* in_pts    = (const float*)d_in[1];
    const float* in_mask   = (const float*)d_in[2];
    const float* in_time   = (const float*)d_in[3];
    const float* enc_w1    = (const float*)d_in[4];
    const float* enc_b1    = (const float*)d_in[5];
    const float* enc_w2    = (const float*)d_in[6];
    const float* enc_b2    = (const float*)d_in[7];
    const float* four_w1   = (const float*)d_in[8];
    const float* four_w2   = (const float*)d_in[9];
    const float* time_w    = (const float*)d_in[10];
    const float* loc1_w1   = (const float*)d_in[11];
    const float* loc1_b1   = (const float*)d_in[12];
    const float* loc1_w2   = (const float*)d_in[13];
    const float* loc1_b2   = (const float*)d_in[14];
    const float* loc2_w1   = (const float*)d_in[15];
    const float* loc2_b1   = (const float*)d_in[16];
    const float* loc2_w2   = (const float*)d_in[17];
    const float* loc2_b2   = (const float*)d_in[18];
    const float* qkv_w     = (const float*)d_in[19];
    const float* qkv_b     = (const float*)d_in[20];
    const float* out_w     = (const float*)d_in[21];
    const float* out_b     = (const float*)d_in[22];
    const float* ln1_g     = (const float*)d_in[23];
    const float* ln1_b     = (const float*)d_in[24];
    const float* ff1_w     = (const float*)d_in[25];
    const float* ff1_b     = (const float*)d_in[26];
    const float* ff2_w     = (const float*)d_in[27];
    const float* ff2_b     = (const float*)d_in[28];
    const float* gammaW    = (const float*)d_in[29];
    const float* ln2_g     = (const float*)d_in[30];
    const float* ln2_b     = (const float*)d_in[31];

    float *pScale,*pShift,*pEnc,*pLf,*pX,*pSkip,*pBufFF,*pTmp,*pQKV,*pAtt,*pLocal,*pHid,*pOut2,*pW1p;
    int *pIdx;
    cudaGetSymbolAddress((void**)&pScale, gScale);
    cudaGetSymbolAddress((void**)&pShift, gShift);
    cudaGetSymbolAddress((void**)&pEnc,   gEnc);
    cudaGetSymbolAddress((void**)&pLf,    gLf);
    cudaGetSymbolAddress((void**)&pX,     gXbuf);
    cudaGetSymbolAddress((void**)&pSkip,  gSkip);
    cudaGetSymbolAddress((void**)&pBufFF, gBufFF);
    cudaGetSymbolAddress((void**)&pTmp,   gTmp);
    cudaGetSymbolAddress((void**)&pQKV,   gQKV);
    cudaGetSymbolAddress((void**)&pAtt,   gAtt);
    cudaGetSymbolAddress((void**)&pLocal, gLocal);
    cudaGetSymbolAddress((void**)&pHid,   gHid);
    cudaGetSymbolAddress((void**)&pOut2,  gOut2);
    cudaGetSymbolAddress((void**)&pW1p,   gW1p);
    cudaGetSymbolAddress((void**)&pIdx,   gIdx);

    // KNN-256 needs 132 KB dynamic smem
    int knn2_smem = (128*257 + 128 + 4)*4 + 32;
    cudaFuncSetAttribute(knn_kernel<256>, cudaFuncAttributeMaxDynamicSharedMemorySize, knn2_smem);
    int knn1_smem = (128*2 + 128 + 4)*4 + 32;

    // --- time embedding + encoder ---
    time_kernel<<<BB, 256>>>(in_time, four_w1, four_w2, time_w, pScale, pShift);
    enc1_kernel<<<TOK, 512>>>(in_feat, enc_w1, enc_b1, pBufFF);
    gemm_launch(TOK, 256, 512, pBufFF, enc_w2, enc_b2, pEnc, true);
    mod_kernel<<<(TOK*DD)/256, 256>>>(pEnc, in_mask, pScale, pShift);

    // --- local features 1 (KNN in 2D point space, MLP on raw features) ---
    knn_kernel<2><<<BB, 128, knn1_smem>>>(in_pts, in_mask, pIdx);
    gather1_kernel<<<(ROWS2*32)/256, 256>>>(in_feat, pIdx, pLocal);
    padw1_kernel<<<(32*512)/256, 256>>>(loc1_w1, pW1p);
    gemm_launch(ROWS2, 512, 32,  pLocal, pW1p,    loc1_b1, pHid,  true);
    gemm_launch(ROWS2, 256, 512, pHid,   loc1_w2, loc1_b2, pOut2, true);
    reduce_mean_kernel<<<(TOK*DD)/256, 256>>>(pOut2, nullptr, pLf, nullptr);

    // --- local features 2 (KNN in 256-dim lf space) ---
    knn_kernel<256><<<BB, 128, knn2_smem>>>(pLf, in_mask, pIdx);
    {
        size_t tot = (size_t)ROWS2*512;
        gather2_kernel<<<(unsigned)((tot + 255)/256), 256>>>(pLf, pIdx, pLocal);
    }
    gemm_launch(ROWS2, 512, 512, pLocal, loc2_w1, loc2_b1, pHid,  true);
    gemm_launch(ROWS2, 256, 512, pHid,   loc2_w2, loc2_b2, pOut2, true);
    reduce_mean_kernel<<<(TOK*DD)/256, 256>>>(pOut2, pEnc, pX, pSkip);

    // --- transformer layers ---
    for (int l = 0; l < LL; l++){
        gemm_launch(TOK, 768, 256, pX, qkv_w + (size_t)l*256*768, qkv_b + l*768, pQKV, false);
        attn_kernel<<<BB*HH, 128>>>(pQKV, in_mask, pAtt);
        gemm_launch(TOK, 256, 256, pAtt, out_w + (size_t)l*256*256, out_b + l*256, pTmp, false);
        ln_kernel<<<TOK, 256>>>(pX, pTmp, ln1_g + l*256, ln1_b + l*256, nullptr, in_mask, pX);
        gemm_launch(TOK, 512, 256, pX, ff1_w + (size_t)l*256*512, ff1_b + l*512, pBufFF, true);
        gemm_launch(TOK, 256, 512, pBufFF, ff2_w + (size_t)l*512*256, ff2_b + l*256, pTmp, false);
        ln_kernel<<<TOK, 256>>>(pX, pTmp, ln2_g + l*256, ln2_b + l*256, gammaW + l*256, in_mask, pX);
    }

    // --- final skip add ---
    add_kernel<<<(TOK*DD)/256, 256>>>(pX, pSkip, (float*)d_out);
}

// round 14
// speedup vs baseline: 1.2293x; 1.2293x over previous
#include <cuda_runtime.h>
#include <math.h>
#include <stdint.h>

// ---------------- problem constants ----------------
#define BB   128
#define NN   128
#define FDIM 13
#define DD   256
#define HH   8
#define LL   8
#define KKN  10
#define FFN  512
#define TOK  (BB*NN)       // 16384
#define ROWS2 (TOK*KKN)    // 163840

// ---------------- scratch (device globals; no allocations allowed) ----------
__device__ float gScale[BB*DD];
__device__ float gShift[BB*DD];
__device__ float gEnc [TOK*DD];
__device__ float gLf  [TOK*DD];
__device__ float gXbuf[TOK*DD];
__device__ float gSkip[TOK*DD];
__device__ float gBufFF[TOK*FFN];
__device__ float gTmp [TOK*DD];
__device__ float gQKV [TOK*3*DD];
__device__ float gAtt [TOK*DD];
__device__ float gP   [TOK*FFN];             // per-token top projection
__device__ float gQ   [TOK*FFN];             // per-token bottom projection (+bias)
__device__ float gHid [(size_t)ROWS2*FFN];   // 335 MB
__device__ float gOut2[(size_t)ROWS2*DD];    // 168 MB
__device__ float gZB  [768];                 // zero bias (device globals are zero-init)
__device__ int   gIdx [TOK*KKN];

// ---------------- math helpers ----------------
__device__ __forceinline__ float geluf(float x){
    float x3 = x*x*x;
    return 0.5f*x*(1.f + tanhf(0.7978845608028654f*(x + 0.044715f*x3)));
}
__device__ __forceinline__ float siluf(float x){
    return x / (1.f + expf(-x));
}
__device__ __forceinline__ float blockReduce256(float v, float* scr){
    #pragma unroll
    for (int o=16;o;o>>=1) v += __shfl_xor_sync(0xffffffffu, v, o);
    if ((threadIdx.x & 31) == 0) scr[threadIdx.x>>5] = v;
    __syncthreads();
    if (threadIdx.x < 32){
        float x = (threadIdx.x < 8) ? scr[threadIdx.x] : 0.f;
        #pragma unroll
        for (int o=4;o;o>>=1) x += __shfl_xor_sync(0xffffffffu, x, o);
        if (threadIdx.x == 0) scr[0] = x;
    }
    __syncthreads();
    float r = scr[0];
    __syncthreads();
    return r;
}

// ------ double-buffered tiled SGEMM: C = A(MxK)@B(KxN) + bias, opt. GELU ----
// Requires M%128==0, N%128==0, K%8==0 (true for all call sites).
#define GBM 128
#define GBN 128
#define GBK 8
template<int EPI>
__global__ void __launch_bounds__(256) sgemm_kernel(int M, int N, int K,
        const float* __restrict__ A, const float* __restrict__ B,
        const float* __restrict__ bias, float* __restrict__ C){
    __shared__ float As[2][GBK][GBM];
    __shared__ float Bs[2][GBK][GBN];
    int tid = threadIdx.x;
    int br = blockIdx.y, bc = blockIdx.x;
    const float* Ag = A + (size_t)br*GBM*K;
    const float* Bg = B + bc*GBN;
    float* Cg = C + (size_t)br*GBM*N + bc*GBN;
    int aRow = tid >> 1, aCol = (tid & 1) << 2;
    int bRow = tid >> 5, bCol = (tid & 31) << 2;
    int tr = (tid >> 4) << 3, tc = (tid & 15) << 3;
    float acc[8][8] = {};
    int ntiles = K / GBK;

    // preload tile 0
    {
        float4 a4 = *reinterpret_cast<const float4*>(Ag + (size_t)aRow*K + aCol);
        As[0][aCol+0][aRow]=a4.x; As[0][aCol+1][aRow]=a4.y;
        As[0][aCol+2][aRow]=a4.z; As[0][aCol+3][aRow]=a4.w;
        float4 b4 = *reinterpret_cast<const float4*>(Bg + (size_t)bRow*N + bCol);
        *reinterpret_cast<float4*>(&Bs[0][bRow][bCol]) = b4;
    }
    __syncthreads();

    for (int t = 0; t < ntiles; t++){
        int cur = t & 1;
        float4 an, bn4;
        if (t + 1 < ntiles){
            an  = *reinterpret_cast<const float4*>(Ag + (size_t)aRow*K + (t+1)*GBK + aCol);
            bn4 = *reinterpret_cast<const float4*>(Bg + (size_t)((t+1)*GBK + bRow)*N + bCol);
        }
        #pragma unroll
        for (int k=0;k<GBK;k++){
            float4 m0 = *reinterpret_cast<const float4*>(&As[cur][k][tr]);
            float4 m1 = *reinterpret_cast<const float4*>(&As[cur][k][tr+4]);
            float4 n0 = *reinterpret_cast<const float4*>(&Bs[cur][k][tc]);
            float4 n1 = *reinterpret_cast<const float4*>(&Bs[cur][k][tc+4]);
            float rm[8]={m0.x,m0.y,m0.z,m0.w,m1.x,m1.y,m1.z,m1.w};
            float rn[8]={n0.x,n0.y,n0.z,n0.w,n1.x,n1.y,n1.z,n1.w};
            #pragma unroll
            for (int i=0;i<8;i++)
                #pragma unroll
                for (int j=0;j<8;j++) acc[i][j] += rm[i]*rn[j];
        }
        if (t + 1 < ntiles){
            int nxt = cur ^ 1;
            As[nxt][aCol+0][aRow]=an.x; As[nxt][aCol+1][aRow]=an.y;
            As[nxt][aCol+2][aRow]=an.z; As[nxt][aCol+3][aRow]=an.w;
            *reinterpret_cast<float4*>(&Bs[nxt][bRow][bCol]) = bn4;
            __syncthreads();
        }
    }
    #pragma unroll
    for (int i=0;i<8;i++){
        float* crow = Cg + (size_t)(tr+i)*N + tc;
        #pragma unroll
        for (int j=0;j<8;j+=4){
            float4 v;
            v.x = acc[i][j+0] + bias[bc*GBN + tc + j + 0];
            v.y = acc[i][j+1] + bias[bc*GBN + tc + j + 1];
            v.z = acc[i][j+2] + bias[bc*GBN + tc + j + 2];
            v.w = acc[i][j+3] + bias[bc*GBN + tc + j + 3];
            if (EPI == 1){ v.x=geluf(v.x); v.y=geluf(v.y); v.z=geluf(v.z); v.w=geluf(v.w); }
            *reinterpret_cast<float4*>(crow + j) = v;
        }
    }
}

// ---------------- time embedding (per batch) ----------------
__global__ void time_kernel(const float* __restrict__ tin,
        const float* __restrict__ fw1, const float* __restrict__ fw2,
        const float* __restrict__ tw, float* __restrict__ scale,
        float* __restrict__ shift){
    __shared__ float e[256];
    __shared__ float hbuf[512];
    __shared__ float tb[256];
    int b = blockIdx.x, tid = threadIdx.x;  // 256 threads
    float t = tin[b];
    if (tid < 128){
        float emb = 9.210340371976184f / 127.f;   // log(1e4)/(half-1)
        float fr = expf(-emb * (float)tid);
        float ang = t * fr * 1000.f;
        e[tid]      = sinf(ang);
        e[tid+128]  = cosf(ang);
    }
    __syncthreads();
    for (int jj = tid; jj < 512; jj += 256){
        float a = 0.f;
        for (int i=0;i<256;i++) a += e[i]*fw1[i*512+jj];
        hbuf[jj] = siluf(a);
    }
    __syncthreads();
    {
        float a = 0.f;
        for (int i=0;i<512;i++) a += hbuf[i]*fw2[i*256+tid];
        tb[tid] = siluf(a);
    }
    __syncthreads();
    for (int jj = tid; jj < 512; jj += 256){
        float a = 0.f;
        for (int i=0;i<256;i++) a += tb[i]*tw[i*512+jj];
        if (jj < 256) scale[b*256+jj] = a;
        else          shift[b*256+jj-256] = a;
    }
}

// ---------------- encoder layer 1 (K=13, fused gelu) ----------------
__global__ void enc1_kernel(const float* __restrict__ feats,
        const float* __restrict__ w1, const float* __restrict__ b1,
        float* __restrict__ outp){
    __shared__ float f[FDIM];
    int bn = blockIdx.x, j = threadIdx.x; // 512 threads
    if (j < FDIM) f[j] = feats[(size_t)bn*FDIM + j];
    __syncthreads();
    float acc = b1[j];
    #pragma unroll
    for (int i=0;i<FDIM;i++) acc += f[i]*w1[i*512+j];
    outp[(size_t)bn*512 + j] = geluf(acc);
}

// -------- loc1 per-token projections: P = f@W1[0:13], Q = f@W1[13:26] + b1 --
__global__ void locpre1_kernel(const float* __restrict__ feats,
        const float* __restrict__ w1, const float* __restrict__ b1,
        float* __restrict__ P, float* __restrict__ Q){
    __shared__ float f[FDIM];
    int bn = blockIdx.x, j = threadIdx.x; // 512 threads
    if (j < FDIM) f[j] = feats[(size_t)bn*FDIM + j];
    __syncthreads();
    float top = 0.f, bot = 0.f;
    #pragma unroll
    for (int i=0;i<FDIM;i++){
        float fv = f[i];
        top += fv * w1[i*512 + j];
        bot += fv * w1[(FDIM+i)*512 + j];
    }
    P[(size_t)bn*512 + j] = top;
    Q[(size_t)bn*512 + j] = bot + b1[j];
}

// -------- expand: hid[bn,k,j] = gelu(P[nbr] - P[bn] + Q[bn]) ---------------
__global__ void expand_kernel(const float* __restrict__ P,
        const float* __restrict__ Q, const int* __restrict__ idx,
        float* __restrict__ outp){
    int i = blockIdx.x*blockDim.x + threadIdx.x;   // float4 index, < ROWS2*128
    int r = i >> 7;          // row in [0, ROWS2)
    int c4 = (i & 127) << 2; // column base
    int bn = r / KKN;        // token
    int b = bn >> 7;
    int nb = idx[r];         // neighbor index within batch
    const float4 pn = *reinterpret_cast<const float4*>(P + ((size_t)(b*128+nb)*512 + c4));
    const float4 pc = *reinterpret_cast<const float4*>(P + ((size_t)bn*512 + c4));
    const float4 q  = *reinterpret_cast<const float4*>(Q + ((size_t)bn*512 + c4));
    float4 v;
    v.x = geluf(pn.x - pc.x + q.x);
    v.y = geluf(pn.y - pc.y + q.y);
    v.z = geluf(pn.z - pc.z + q.z);
    v.w = geluf(pn.w - pc.w + q.w);
    *reinterpret_cast<float4*>(outp + ((size_t)r*512 + c4)) = v;
}

// ---------------- modulation: enc = enc*(1+m*scale)+m*shift ----------------
__global__ void mod_kernel(float* enc, const float* __restrict__ mask,
        const float* __restrict__ sc, const float* __restrict__ sh){
    int idx = blockIdx.x*blockDim.x + threadIdx.x;
    if (idx >= TOK*DD) return;
    int c = idx & 255, bn = idx >> 8, b = bn >> 7;
    float m = mask[bn];
    enc[idx] = enc[idx]*(1.f + m*sc[b*256+c]) + m*sh[b*256+c];
}

// ---------------- KNN (per batch block, 128 threads, thread=m) --------------
template<int DIM>
__global__ void knn_kernel(const float* __restrict__ pts,
        const float* __restrict__ mask, int* __restrict__ idxout){
    constexpr int P = (DIM == 2) ? 2 : (DIM + 1);
    extern __shared__ float sm[];
    float* qs = sm;                  // 128*P
    float* rs = qs + 128*P;          // 128
    float* wv = rs + 128;            // 4
    int*   wi = (int*)(wv + 4);      // 4
    int*   win = wi + 4;             // 1
    int b = blockIdx.x, tid = threadIdx.x;
    for (int t = tid; t < 128*DIM; t += 128){
        int m = t / DIM, i = t - m*DIM;
        qs[m*P+i] = pts[(size_t)(b*128+m)*DIM + i] + 999.f*(1.f - mask[b*128+m]);
    }
    __syncthreads();
    {
        float s = 0.f;
        for (int i=0;i<DIM;i++){ float v = qs[tid*P+i]; s += v*v; }
        rs[tid] = s;
    }
    __syncthreads();
    for (int n=0;n<128;n++){
        float dot = 0.f;
        for (int i=0;i<DIM;i++) dot += qs[n*P+i]*qs[tid*P+i];
        float myd = (rs[n] - 2.f*dot) + rs[tid];
        for (int rsel=0; rsel<KKN+1; rsel++){
            float v = myd; int ii = tid;
            #pragma unroll
            for (int off=16; off; off>>=1){
                float ov = __shfl_down_sync(0xffffffffu, v, off);
                int   oi = __shfl_down_sync(0xffffffffu, ii, off);
                if (ov < v || (ov == v && oi < ii)){ v = ov; ii = oi; }
            }
            if ((tid & 31) == 0){ wv[tid>>5] = v; wi[tid>>5] = ii; }
            __syncthreads();
            if (tid == 0){
                float bv = wv[0]; int bi = wi[0];
                #pragma unroll
                for (int w=1; w<4; w++)
                    if (wv[w] < bv || (wv[w]==bv && wi[w]<bi)){ bv=wv[w]; bi=wi[w]; }
                *win = bi;
                if (rsel >= 1) idxout[(size_t)(b*128+n)*KKN + (rsel-1)] = bi;
            }
            __syncthreads();
            if (tid == *win) myd = 3.0e38f;
        }
        __syncthreads();
    }
}

// ---------------- mean over K (optionally add enc, dual write) -------------
__global__ void reduce_mean_kernel(const float* __restrict__ in,
        const float* __restrict__ addsrc, float* __restrict__ out,
        float* __restrict__ out2){
    int idx = blockIdx.x*blockDim.x + threadIdx.x;
    if (idx >= TOK*DD) return;
    int bn = idx >> 8, c = idx & 255;
    const float* p = in + ((size_t)bn*KKN)*256 + c;
    float s = 0.f;
    #pragma unroll
    for (int k=0;k<KKN;k++) s += p[(size_t)k*256];
    s *= (1.f/KKN);
    if (addsrc){
        float v = addsrc[idx] + s;
        out[idx] = v;
        out2[idx] = v;
    } else {
        out[idx] = s;
    }
}

// ---------------- attention (per (b,h) block; two-pass softmax) -------------
__global__ void __launch_bounds__(128) attn_kernel(const float* __restrict__ qkv,
        const float* __restrict__ mask, float* __restrict__ outp){
    __shared__ float Ks[128*32];
    __shared__ float Vs[128*32];
    __shared__ float Ms[128];
    int b = blockIdx.x >> 3, h = blockIdx.x & 7;
    int tid = threadIdx.x; // 128
    const float* base = qkv + (size_t)b*128*768;
    for (int t = tid; t < 128*8; t += 128){
        int m = t >> 3, dq = (t & 7) << 2;
        *reinterpret_cast<float4*>(&Ks[m*32+dq]) =
            *reinterpret_cast<const float4*>(&base[(size_t)m*768 + 256 + h*32 + dq]);
        *reinterpret_cast<float4*>(&Vs[m*32+dq]) =
            *reinterpret_cast<const float4*>(&base[(size_t)m*768 + 512 + h*32 + dq]);
    }
    Ms[tid] = mask[b*128+tid];
    float q[32];
    #pragma unroll
    for (int d=0; d<32; d+=4)
        *reinterpret_cast<float4*>(&q[d]) =
            *reinterpret_cast<const float4*>(&base[(size_t)tid*768 + h*32 + d]);
    __syncthreads();
    const float scl = 0.17677669529663687f; // 1/sqrt(32)
    float mx = -1e30f;
    for (int m=0;m<128;m++){
        float s = 0.f;
        #pragma unroll
        for (int d=0; d<32; d++) s += q[d]*Ks[m*32+d];
        s = (Ms[m] > 0.f) ? s*scl : -1e9f;
        mx = fmaxf(mx, s);
    }
    float sum = 0.f;
    float acc[32] = {};
    for (int m=0;m<128;m++){
        float s = 0.f;
        #pragma unroll
        for (int d=0; d<32; d++) s += q[d]*Ks[m*32+d];
        s = (Ms[m] > 0.f) ? s*scl : -1e9f;
        float e = expf(s - mx);
        sum += e;
        #pragma unroll
        for (int d=0; d<32; d++) acc[d] += e*Vs[m*32+d];
    }
    float inv = 1.f/sum;
    float* o = outp + (size_t)(b*128+tid)*256 + h*32;
    #pragma unroll
    for (int d=0; d<32; d+=4){
        float4 v; v.x=acc[d]*inv; v.y=acc[d+1]*inv; v.z=acc[d+2]*inv; v.w=acc[d+3]*inv;
        *reinterpret_cast<float4*>(o + d) = v;
    }
}

// ---------------- residual + LayerNorm (optional gamma*mask on t) -----------
__global__ void ln_kernel(const float* res, const float* t,
        const float* __restrict__ g, const float* __restrict__ bb,
        const float* __restrict__ gamma, const float* __restrict__ mask,
        float* outp){
    __shared__ float scr[8];
    int bn = blockIdx.x, c = threadIdx.x; // 256 threads
    size_t off = (size_t)bn*256 + c;
    float hv = t[off];
    if (gamma) hv *= gamma[c] * mask[bn];
    float v = res[off] + hv;
    float mean = blockReduce256(v, scr) * (1.f/256.f);
    float d = v - mean;
    float var = blockReduce256(d*d, scr) * (1.f/256.f);
    outp[off] = d * rsqrtf(var + 1e-5f) * g[c] + bb[c];
}

// ---------------- final add ----------------
__global__ void add_kernel(const float* __restrict__ a, const float* __restrict__ b,
        float* __restrict__ o){
    int idx = blockIdx.x*blockDim.x + threadIdx.x;
    if (idx >= TOK*DD) return;
    o[idx] = a[idx] + b[idx];
}

// ---------------- host ----------------
static void gemm_launch(int M, int N, int K, const float* A, const float* B,
                        const float* bias, float* C, bool ge){
    dim3 grid(N/128, M/128);
    if (ge) sgemm_kernel<1><<<grid, 256>>>(M, N, K, A, B, bias, C);
    else    sgemm_kernel<0><<<grid, 256>>>(M, N, K, A, B, bias, C);
}

extern "C" void kernel_launch(void* const* d_in, const int* in_sizes, int n_in,
                              void* d_out, int out_size){
    const float* in_feat   = (const float*)d_in[0];
    const float* in_pts    = (const float*)d_in[1];
    const float* in_mask   = (const float*)d_in[2];
    const float* in_time   = (const float*)d_in[3];
    const float* enc_w1    = (const float*)d_in[4];
    const float* enc_b1    = (const float*)d_in[5];
    const float* enc_w2    = (const float*)d_in[6];
    const float* enc_b2    = (const float*)d_in[7];
    const float* four_w1   = (const float*)d_in[8];
    const float* four_w2   = (const float*)d_in[9];
    const float* time_w    = (const float*)d_in[10];
    const float* loc1_w1   = (const float*)d_in[11];
    const float* loc1_b1   = (const float*)d_in[12];
    const float* loc1_w2   = (const float*)d_in[13];
    const float* loc1_b2   = (const float*)d_in[14];
    const float* loc2_w1   = (const float*)d_in[15];
    const float* loc2_b1   = (const float*)d_in[16];
    const float* loc2_w2   = (const float*)d_in[17];
    const float* loc2_b2   = (const float*)d_in[18];
    const float* qkv_w     = (const float*)d_in[19];
    const float* qkv_b     = (const float*)d_in[20];
    const float* out_w     = (const float*)d_in[21];
    const float* out_b     = (const float*)d_in[22];
    const float* ln1_g     = (const float*)d_in[23];
    const float* ln1_b     = (const float*)d_in[24];
    const float* ff1_w     = (const float*)d_in[25];
    const float* ff1_b     = (const float*)d_in[26];
    const float* ff2_w     = (const float*)d_in[27];
    const float* ff2_b     = (const float*)d_in[28];
    const float* gammaW    = (const float*)d_in[29];
    const float* ln2_g     = (const float*)d_in[30];
    const float* ln2_b     = (const float*)d_in[31];

    float *pScale,*pShift,*pEnc,*pLf,*pX,*pSkip,*pBufFF,*pTmp,*pQKV,*pAtt,*pP,*pQ,*pHid,*pOut2,*pZB;
    int *pIdx;
    cudaGetSymbolAddress((void**)&pScale, gScale);
    cudaGetSymbolAddress((void**)&pShift, gShift);
    cudaGetSymbolAddress((void**)&pEnc,   gEnc);
    cudaGetSymbolAddress((void**)&pLf,    gLf);
    cudaGetSymbolAddress((void**)&pX,     gXbuf);
    cudaGetSymbolAddress((void**)&pSkip,  gSkip);
    cudaGetSymbolAddress((void**)&pBufFF, gBufFF);
    cudaGetSymbolAddress((void**)&pTmp,   gTmp);
    cudaGetSymbolAddress((void**)&pQKV,   gQKV);
    cudaGetSymbolAddress((void**)&pAtt,   gAtt);
    cudaGetSymbolAddress((void**)&pP,     gP);
    cudaGetSymbolAddress((void**)&pQ,     gQ);
    cudaGetSymbolAddress((void**)&pHid,   gHid);
    cudaGetSymbolAddress((void**)&pOut2,  gOut2);
    cudaGetSymbolAddress((void**)&pZB,    gZB);
    cudaGetSymbolAddress((void**)&pIdx,   gIdx);

    // KNN-256 needs 132 KB dynamic smem
    int knn2_smem = (128*257 + 128 + 4)*4 + 32;
    cudaFuncSetAttribute(knn_kernel<256>, cudaFuncAttributeMaxDynamicSharedMemorySize, knn2_smem);
    int knn1_smem = (128*2 + 128 + 4)*4 + 32;

    const int EXP_BLOCKS = (ROWS2*128)/256;   // expand kernel: float4 granularity

    // --- time embedding + encoder ---
    time_kernel<<<BB, 256>>>(in_time, four_w1, four_w2, time_w, pScale, pShift);
    enc1_kernel<<<TOK, 512>>>(in_feat, enc_w1, enc_b1, pBufFF);
    gemm_launch(TOK, 256, 512, pBufFF, enc_w2, enc_b2, pEnc, true);
    mod_kernel<<<(TOK*DD)/256, 256>>>(pEnc, in_mask, pScale, pShift);

    // --- local features 1 (KNN in 2D point space, MLP on raw features) ---
    knn_kernel<2><<<BB, 128, knn1_smem>>>(in_pts, in_mask, pIdx);
    locpre1_kernel<<<TOK, 512>>>(in_feat, loc1_w1, loc1_b1, pP, pQ);
    expand_kernel<<<EXP_BLOCKS, 256>>>(pP, pQ, pIdx, pHid);
    gemm_launch(ROWS2, 256, 512, pHid, loc1_w2, loc1_b2, pOut2, true);
    reduce_mean_kernel<<<(TOK*DD)/256, 256>>>(pOut2, nullptr, pLf, nullptr);

    // --- local features 2 (KNN in 256-dim lf space) ---
    knn_kernel<256><<<BB, 128, knn2_smem>>>(pLf, in_mask, pIdx);
    // P2 = lf @ W1[0:256,:]   (zero bias)
    gemm_launch(TOK, 512, 256, pLf, loc2_w1,            pZB,     pP, false);
    // Q2 = lf @ W1[256:512,:] + b1
    gemm_launch(TOK, 512, 256, pLf, loc2_w1 + 256*512,  loc2_b1, pQ, false);
    expand_kernel<<<EXP_BLOCKS, 256>>>(pP, pQ, pIdx, pHid);
    gemm_launch(ROWS2, 256, 512, pHid, loc2_w2, loc2_b2, pOut2, true);
    reduce_mean_kernel<<<(TOK*DD)/256, 256>>>(pOut2, pEnc, pX, pSkip);

    // --- transformer layers ---
    for (int l = 0; l < LL; l++){
        gemm_launch(TOK, 768, 256, pX, qkv_w + (size_t)l*256*768, qkv_b + l*768, pQKV, false);
        attn_kernel<<<BB*HH, 128>>>(pQKV, in_mask, pAtt);
        gemm_launch(TOK, 256, 256, pAtt, out_w + (size_t)l*256*256, out_b + l*256, pTmp, false);
        ln_kernel<<<TOK, 256>>>(pX, pTmp, ln1_g + l*256, ln1_b + l*256, nullptr, in_mask, pX);
        gemm_launch(TOK, 512, 256, pX, ff1_w + (size_t)l*256*512, ff1_b + l*512, pBufFF, true);
        gemm_launch(TOK, 256, 512, pBufFF, ff2_w + (size_t)l*512*256, ff2_b + l*256, pTmp, false);
        ln_kernel<<<TOK, 256>>>(pX, pTmp, ln2_g + l*256, ln2_b + l*256, gammaW + l*256, in_mask, pX);
    }

    // --- final skip add ---
    add_kernel<<<(TOK*DD)/256, 256>>>(pX, pSkip, (float*)d_out);
}

// round 15
// speedup vs baseline: 2.2043x; 1.7932x over previous
#include <cuda_runtime.h>
#include <math.h>
#include <stdint.h>

// ---------------- problem constants ----------------
#define BB   128
#define NN   128
#define FDIM 13
#define DD   256
#define HH   8
#define LL   8
#define KKN  10
#define FFN  512
#define TOK  (BB*NN)       // 16384
#define ROWS2 (TOK*KKN)    // 163840

// ---------------- scratch (device globals; no allocations allowed) ----------
__device__ float gScale[BB*DD];
__device__ float gShift[BB*DD];
__device__ float gEnc [TOK*DD];
__device__ float gLf  [TOK*DD];
__device__ float gXbuf[TOK*DD];
__device__ float gSkip[TOK*DD];
__device__ float gBufFF[TOK*FFN];
__device__ float gTmp [TOK*DD];
__device__ float gQKV [TOK*3*DD];
__device__ float gAtt [TOK*DD];
__device__ float gP   [TOK*FFN];             // per-token top projection
__device__ float gQ   [TOK*FFN];             // per-token bottom projection (+bias)
__device__ float gHid [(size_t)ROWS2*FFN];   // 335 MB
__device__ float gOut2[(size_t)ROWS2*DD];    // 168 MB
__device__ float gZB  [768];                 // zero bias (device globals are zero-init)
__device__ int   gIdx [TOK*KKN];

// ---------------- math helpers ----------------
__device__ __forceinline__ float geluf(float x){
    float x3 = x*x*x;
    return 0.5f*x*(1.f + tanhf(0.7978845608028654f*(x + 0.044715f*x3)));
}
__device__ __forceinline__ float siluf(float x){
    return x / (1.f + expf(-x));
}
__device__ __forceinline__ uint32_t f2tf(float f){
    uint32_t u;
    asm("cvt.rna.tf32.f32 %0, %1;" : "=r"(u) : "f"(f));
    return u;
}
__device__ __forceinline__ float blockReduce256(float v, float* scr){
    #pragma unroll
    for (int o=16;o;o>>=1) v += __shfl_xor_sync(0xffffffffu, v, o);
    if ((threadIdx.x & 31) == 0) scr[threadIdx.x>>5] = v;
    __syncthreads();
    if (threadIdx.x < 32){
        float x = (threadIdx.x < 8) ? scr[threadIdx.x] : 0.f;
        #pragma unroll
        for (int o=4;o;o>>=1) x += __shfl_xor_sync(0xffffffffu, x, o);
        if (threadIdx.x == 0) scr[0] = x;
    }
    __syncthreads();
    float r = scr[0];
    __syncthreads();
    return r;
}

// ---------------- TF32 tensor-core GEMM ----------------
// C = A(MxK) @ B(KxN) + bias, optional GELU.
// Block 128x128, BK=16, 256 threads = 8 warps (2x4), warp tile 64x32.
// mma.sync.aligned.m16n8k8.row.col.f32.tf32.tf32.f32
// Requires M%128==0, N%128==0, K%16==0 (true for all call sites).
#define ASTR 20    // As row stride (floats) — conflict-free fragment loads
#define BSTR 136   // Bs row stride (floats) — conflict-free fragment loads

__device__ __forceinline__ void mma_tf32(float* c, const uint32_t* a,
                                         uint32_t b0, uint32_t b1){
    asm volatile(
        "mma.sync.aligned.m16n8k8.row.col.f32.tf32.tf32.f32 "
        "{%0,%1,%2,%3},{%4,%5,%6,%7},{%8,%9},{%0,%1,%2,%3};"
        : "+f"(c[0]), "+f"(c[1]), "+f"(c[2]), "+f"(c[3])
        : "r"(a[0]), "r"(a[1]), "r"(a[2]), "r"(a[3]), "r"(b0), "r"(b1));
}

template<int EPI>
__global__ void __launch_bounds__(256) tgemm_kernel(int M, int N, int K,
        const float* __restrict__ A, const float* __restrict__ B,
        const float* __restrict__ bias, float* __restrict__ C){
    __shared__ uint32_t As[2][128*ASTR];
    __shared__ uint32_t Bs[2][16*BSTR];
    int tid = threadIdx.x;
    int lane = tid & 31;
    int wid  = tid >> 5;
    int g   = lane >> 2;     // group id 0..7
    int tig = lane & 3;      // thread in group 0..3
    int wm = wid >> 2;       // warp M coord (0..1)
    int wn = wid & 3;        // warp N coord (0..3)
    int br = blockIdx.y, bc = blockIdx.x;
    const float* Ag = A + (size_t)br*128*K;
    const float* Bg = B + (size_t)bc*128;
    float* Cg = C + (size_t)br*128*N + (size_t)bc*128;

    // global-load coordinates (2 float4 each for A and B per thread)
    int aRow0 = tid >> 1;                 // 2 threads per row? no: see below
    (void)aRow0;
    // A tile: 128 rows x 16 cols = 512 float4; idx = tid, tid+256
    // B tile: 16 rows x 128 cols = 512 float4; idx = tid, tid+256

    float acc[4][4][4] = {};

    // ---- fill tile 0 ----
    {
        #pragma unroll
        for (int i=0;i<2;i++){
            int idx = tid + i*256;
            int row = idx >> 2, c4 = (idx & 3) << 2;
            float4 v = *reinterpret_cast<const float4*>(Ag + (size_t)row*K + c4);
            uint32_t* d = &As[0][row*ASTR + c4];
            d[0]=f2tf(v.x); d[1]=f2tf(v.y); d[2]=f2tf(v.z); d[3]=f2tf(v.w);
        }
        #pragma unroll
        for (int i=0;i<2;i++){
            int idx = tid + i*256;
            int row = idx >> 5, c4 = (idx & 31) << 2;
            float4 v = *reinterpret_cast<const float4*>(Bg + (size_t)row*N + c4);
            uint32_t* d = &Bs[0][row*BSTR + c4];
            d[0]=f2tf(v.x); d[1]=f2tf(v.y); d[2]=f2tf(v.z); d[3]=f2tf(v.w);
        }
    }
    __syncthreads();

    int ntiles = K / 16;
    for (int t = 0; t < ntiles; t++){
        int cur = t & 1;
        float4 ap[2], bp[2];
        if (t + 1 < ntiles){
            #pragma unroll
            for (int i=0;i<2;i++){
                int idx = tid + i*256;
                int row = idx >> 2, c4 = (idx & 3) << 2;
                ap[i] = *reinterpret_cast<const float4*>(Ag + (size_t)row*K + (t+1)*16 + c4);
            }
            #pragma unroll
            for (int i=0;i<2;i++){
                int idx = tid + i*256;
                int row = idx >> 5, c4 = (idx & 31) << 2;
                bp[i] = *reinterpret_cast<const float4*>(Bg + (size_t)((t+1)*16 + row)*N + c4);
            }
        }
        // ---- compute on buffer cur: two k-steps of 8 ----
        #pragma unroll
        for (int ks = 0; ks < 2; ks++){
            int k0 = ks * 8;
            uint32_t a[4][4];
            #pragma unroll
            for (int mf = 0; mf < 4; mf++){
                int r0 = (wm*64 + mf*16 + g)*ASTR;
                a[mf][0] = As[cur][r0          + k0 + tig];
                a[mf][1] = As[cur][r0 + 8*ASTR + k0 + tig];
                a[mf][2] = As[cur][r0          + k0 + tig + 4];
                a[mf][3] = As[cur][r0 + 8*ASTR + k0 + tig + 4];
            }
            #pragma unroll
            for (int nf = 0; nf < 4; nf++){
                int cb = wn*32 + nf*8 + g;
                uint32_t b0 = Bs[cur][(k0 + tig    )*BSTR + cb];
                uint32_t b1 = Bs[cur][(k0 + tig + 4)*BSTR + cb];
                #pragma unroll
                for (int mf = 0; mf < 4; mf++)
                    mma_tf32(acc[mf][nf], a[mf], b0, b1);
            }
        }
        if (t + 1 < ntiles){
            int nxt = cur ^ 1;
            #pragma unroll
            for (int i=0;i<2;i++){
                int idx = tid + i*256;
                int row = idx >> 2, c4 = (idx & 3) << 2;
                uint32_t* d = &As[nxt][row*ASTR + c4];
                d[0]=f2tf(ap[i].x); d[1]=f2tf(ap[i].y); d[2]=f2tf(ap[i].z); d[3]=f2tf(ap[i].w);
            }
            #pragma unroll
            for (int i=0;i<2;i++){
                int idx = tid + i*256;
                int row = idx >> 5, c4 = (idx & 31) << 2;
                uint32_t* d = &Bs[nxt][row*BSTR + c4];
                d[0]=f2tf(bp[i].x); d[1]=f2tf(bp[i].y); d[2]=f2tf(bp[i].z); d[3]=f2tf(bp[i].w);
            }
            __syncthreads();
        }
    }

    // ---- epilogue: bias (+ optional GELU), float2 stores ----
    #pragma unroll
    for (int mf = 0; mf < 4; mf++){
        int row0 = wm*64 + mf*16 + g;
        #pragma unroll
        for (int nf = 0; nf < 4; nf++){
            int col = wn*32 + nf*8 + (tig << 1);
            float bx = bias[bc*128 + col];
            float by = bias[bc*128 + col + 1];
            float v0 = acc[mf][nf][0] + bx;
            float v1 = acc[mf][nf][1] + by;
            float v2 = acc[mf][nf][2] + bx;
            float v3 = acc[mf][nf][3] + by;
            if (EPI == 1){
                v0 = geluf(v0); v1 = geluf(v1);
                v2 = geluf(v2); v3 = geluf(v3);
            }
            *reinterpret_cast<float2*>(Cg + (size_t)row0*N + col) = make_float2(v0, v1);
            *reinterpret_cast<float2*>(Cg + (size_t)(row0+8)*N + col) = make_float2(v2, v3);
        }
    }
}

// ---------------- time embedding (per batch) ----------------
__global__ void time_kernel(const float* __restrict__ tin,
        const float* __restrict__ fw1, const float* __restrict__ fw2,
        const float* __restrict__ tw, float* __restrict__ scale,
        float* __restrict__ shift){
    __shared__ float e[256];
    __shared__ float hbuf[512];
    __shared__ float tb[256];
    int b = blockIdx.x, tid = threadIdx.x;  // 256 threads
    float t = tin[b];
    if (tid < 128){
        float emb = 9.210340371976184f / 127.f;   // log(1e4)/(half-1)
        float fr = expf(-emb * (float)tid);
        float ang = t * fr * 1000.f;
        e[tid]      = sinf(ang);
        e[tid+128]  = cosf(ang);
    }
    __syncthreads();
    for (int jj = tid; jj < 512; jj += 256){
        float a = 0.f;
        for (int i=0;i<256;i++) a += e[i]*fw1[i*512+jj];
        hbuf[jj] = siluf(a);
    }
    __syncthreads();
    {
        float a = 0.f;
        for (int i=0;i<512;i++) a += hbuf[i]*fw2[i*256+tid];
        tb[tid] = siluf(a);
    }
    __syncthreads();
    for (int jj = tid; jj < 512; jj += 256){
        float a = 0.f;
        for (int i=0;i<256;i++) a += tb[i]*tw[i*512+jj];
        if (jj < 256) scale[b*256+jj] = a;
        else          shift[b*256+jj-256] = a;
    }
}

// ---------------- encoder layer 1 (K=13, fused gelu) ----------------
__global__ void enc1_kernel(const float* __restrict__ feats,
        const float* __restrict__ w1, const float* __restrict__ b1,
        float* __restrict__ outp){
    __shared__ float f[FDIM];
    int bn = blockIdx.x, j = threadIdx.x; // 512 threads
    if (j < FDIM) f[j] = feats[(size_t)bn*FDIM + j];
    __syncthreads();
    float acc = b1[j];
    #pragma unroll
    for (int i=0;i<FDIM;i++) acc += f[i]*w1[i*512+j];
    outp[(size_t)bn*512 + j] = geluf(acc);
}

// -------- loc1 per-token projections: P = f@W1[0:13], Q = f@W1[13:26] + b1 --
__global__ void locpre1_kernel(const float* __restrict__ feats,
        const float* __restrict__ w1, const float* __restrict__ b1,
        float* __restrict__ P, float* __restrict__ Q){
    __shared__ float f[FDIM];
    int bn = blockIdx.x, j = threadIdx.x; // 512 threads
    if (j < FDIM) f[j] = feats[(size_t)bn*FDIM + j];
    __syncthreads();
    float top = 0.f, bot = 0.f;
    #pragma unroll
    for (int i=0;i<FDIM;i++){
        float fv = f[i];
        top += fv * w1[i*512 + j];
        bot += fv * w1[(FDIM+i)*512 + j];
    }
    P[(size_t)bn*512 + j] = top;
    Q[(size_t)bn*512 + j] = bot + b1[j];
}

// -------- expand: hid[bn,k,j] = gelu(P[nbr] - P[bn] + Q[bn]) ---------------
__global__ void expand_kernel(const float* __restrict__ P,
        const float* __restrict__ Q, const int* __restrict__ idx,
        float* __restrict__ outp){
    int i = blockIdx.x*blockDim.x + threadIdx.x;   // float4 index, < ROWS2*128
    int r = i >> 7;          // row in [0, ROWS2)
    int c4 = (i & 127) << 2; // column base
    int bn = r / KKN;        // token
    int b = bn >> 7;
    int nb = idx[r];         // neighbor index within batch
    const float4 pn = *reinterpret_cast<const float4*>(P + ((size_t)(b*128+nb)*512 + c4));
    const float4 pc = *reinterpret_cast<const float4*>(P + ((size_t)bn*512 + c4));
    const float4 q  = *reinterpret_cast<const float4*>(Q + ((size_t)bn*512 + c4));
    float4 v;
    v.x = geluf(pn.x - pc.x + q.x);
    v.y = geluf(pn.y - pc.y + q.y);
    v.z = geluf(pn.z - pc.z + q.z);
    v.w = geluf(pn.w - pc.w + q.w);
    *reinterpret_cast<float4*>(outp + ((size_t)r*512 + c4)) = v;
}

// ---------------- modulation: enc = enc*(1+m*scale)+m*shift ----------------
__global__ void mod_kernel(float* enc, const float* __restrict__ mask,
        const float* __restrict__ sc, const float* __restrict__ sh){
    int idx = blockIdx.x*blockDim.x + threadIdx.x;
    if (idx >= TOK*DD) return;
    int c = idx & 255, bn = idx >> 8, b = bn >> 7;
    float m = mask[bn];
    enc[idx] = enc[idx]*(1.f + m*sc[b*256+c]) + m*sh[b*256+c];
}

// ---------------- KNN (per batch block, 128 threads, thread=m) --------------
template<int DIM>
__global__ void knn_kernel(const float* __restrict__ pts,
        const float* __restrict__ mask, int* __restrict__ idxout){
    constexpr int P = (DIM == 2) ? 2 : (DIM + 1);
    extern __shared__ float sm[];
    float* qs = sm;                  // 128*P
    float* rs = qs + 128*P;          // 128
    float* wv = rs + 128;            // 4
    int*   wi = (int*)(wv + 4);      // 4
    int*   win = wi + 4;             // 1
    int b = blockIdx.x, tid = threadIdx.x;
    for (int t = tid; t < 128*DIM; t += 128){
        int m = t / DIM, i = t - m*DIM;
        qs[m*P+i] = pts[(size_t)(b*128+m)*DIM + i] + 999.f*(1.f - mask[b*128+m]);
    }
    __syncthreads();
    {
        float s = 0.f;
        for (int i=0;i<DIM;i++){ float v = qs[tid*P+i]; s += v*v; }
        rs[tid] = s;
    }
    __syncthreads();
    for (int n=0;n<128;n++){
        float dot = 0.f;
        for (int i=0;i<DIM;i++) dot += qs[n*P+i]*qs[tid*P+i];
        float myd = (rs[n] - 2.f*dot) + rs[tid];
        for (int rsel=0; rsel<KKN+1; rsel++){
            float v = myd; int ii = tid;
            #pragma unroll
            for (int off=16; off; off>>=1){
                float ov = __shfl_down_sync(0xffffffffu, v, off);
                int   oi = __shfl_down_sync(0xffffffffu, ii, off);
                if (ov < v || (ov == v && oi < ii)){ v = ov; ii = oi; }
            }
            if ((tid & 31) == 0){ wv[tid>>5] = v; wi[tid>>5] = ii; }
            __syncthreads();
            if (tid == 0){
                float bv = wv[0]; int bi = wi[0];
                #pragma unroll
                for (int w=1; w<4; w++)
                    if (wv[w] < bv || (wv[w]==bv && wi[w]<bi)){ bv=wv[w]; bi=wi[w]; }
                *win = bi;
                if (rsel >= 1) idxout[(size_t)(b*128+n)*KKN + (rsel-1)] = bi;
            }
            __syncthreads();
            if (tid == *win) myd = 3.0e38f;
        }
        __syncthreads();
    }
}

// ---------------- mean over K (optionally add enc, dual write) -------------
__global__ void reduce_mean_kernel(const float* __restrict__ in,
        const float* __restrict__ addsrc, float* __restrict__ out,
        float* __restrict__ out2){
    int idx = blockIdx.x*blockDim.x + threadIdx.x;
    if (idx >= TOK*DD) return;
    int bn = idx >> 8, c = idx & 255;
    const float* p = in + ((size_t)bn*KKN)*256 + c;
    float s = 0.f;
    #pragma unroll
    for (int k=0;k<KKN;k++) s += p[(size_t)k*256];
    s *= (1.f/KKN);
    if (addsrc){
        float v = addsrc[idx] + s;
        out[idx] = v;
        out2[idx] = v;
    } else {
        out[idx] = s;
    }
}

// ---------------- attention (per (b,h) block; two-pass softmax) -------------
__global__ void __launch_bounds__(128) attn_kernel(const float* __restrict__ qkv,
        const float* __restrict__ mask, float* __restrict__ outp){
    __shared__ float Ks[128*32];
    __shared__ float Vs[128*32];
    __shared__ float Ms[128];
    int b = blockIdx.x >> 3, h = blockIdx.x & 7;
    int tid = threadIdx.x; // 128
    const float* base = qkv + (size_t)b*128*768;
    for (int t = tid; t < 128*8; t += 128){
        int m = t >> 3, dq = (t & 7) << 2;
        *reinterpret_cast<float4*>(&Ks[m*32+dq]) =
            *reinterpret_cast<const float4*>(&base[(size_t)m*768 + 256 + h*32 + dq]);
        *reinterpret_cast<float4*>(&Vs[m*32+dq]) =
            *reinterpret_cast<const float4*>(&base[(size_t)m*768 + 512 + h*32 + dq]);
    }
    Ms[tid] = mask[b*128+tid];
    float q[32];
    #pragma unroll
    for (int d=0; d<32; d+=4)
        *reinterpret_cast<float4*>(&q[d]) =
            *reinterpret_cast<const float4*>(&base[(size_t)tid*768 + h*32 + d]);
    __syncthreads();
    const float scl = 0.17677669529663687f; // 1/sqrt(32)
    float mx = -1e30f;
    for (int m=0;m<128;m++){
        float s = 0.f;
        #pragma unroll
        for (int d=0; d<32; d++) s += q[d]*Ks[m*32+d];
        s = (Ms[m] > 0.f) ? s*scl : -1e9f;
        mx = fmaxf(mx, s);
    }
    float sum = 0.f;
    float acc[32] = {};
    for (int m=0;m<128;m++){
        float s = 0.f;
        #pragma unroll
        for (int d=0; d<32; d++) s += q[d]*Ks[m*32+d];
        s = (Ms[m] > 0.f) ? s*scl : -1e9f;
        float e = expf(s - mx);
        sum += e;
        #pragma unroll
        for (int d=0; d<32; d++) acc[d] += e*Vs[m*32+d];
    }
    float inv = 1.f/sum;
    float* o = outp + (size_t)(b*128+tid)*256 + h*32;
    #pragma unroll
    for (int d=0; d<32; d+=4){
        float4 v; v.x=acc[d]*inv; v.y=acc[d+1]*inv; v.z=acc[d+2]*inv; v.w=acc[d+3]*inv;
        *reinterpret_cast<float4*>(o + d) = v;
    }
}

// ---------------- residual + LayerNorm (optional gamma*mask on t) -----------
__global__ void ln_kernel(const float* res, const float* t,
        const float* __restrict__ g, const float* __restrict__ bb,
        const float* __restrict__ gamma, const float* __restrict__ mask,
        float* outp){
    __shared__ float scr[8];
    int bn = blockIdx.x, c = threadIdx.x; // 256 threads
    size_t off = (size_t)bn*256 + c;
    float hv = t[off];
    if (gamma) hv *= gamma[c] * mask[bn];
    float v = res[off] + hv;
    float mean = blockReduce256(v, scr) * (1.f/256.f);
    float d = v - mean;
    float var = blockReduce256(d*d, scr) * (1.f/256.f);
    outp[off] = d * rsqrtf(var + 1e-5f) * g[c] + bb[c];
}

// ---------------- final add ----------------
__global__ void add_kernel(const float* __restrict__ a, const float* __restrict__ b,
        float* __restrict__ o){
    int idx = blockIdx.x*blockDim.x + threadIdx.x;
    if (idx >= TOK*DD) return;
    o[idx] = a[idx] + b[idx];
}

// ---------------- host ----------------
static void gemm_launch(int M, int N, int K, const float* A, const float* B,
                        const float* bias, float* C, bool ge){
    dim3 grid(N/128, M/128);
    if (ge) tgemm_kernel<1><<<grid, 256>>>(M, N, K, A, B, bias, C);
    else    tgemm_kernel<0><<<grid, 256>>>(M, N, K, A, B, bias, C);
}

extern "C" void kernel_launch(void* const* d_in, const int* in_sizes, int n_in,
                              void* d_out, int out_size){
    const float* in_feat   = (const float*)d_in[0];
    const float* in_pts    = (const float*)d_in[1];
    const float* in_mask   = (const float*)d_in[2];
    const float* in_time   = (const float*)d_in[3];
    const float* enc_w1    = (const float*)d_in[4];
    const float* enc_b1    = (const float*)d_in[5];
    const float* enc_w2    = (const float*)d_in[6];
    const float* enc_b2    = (const float*)d_in[7];
    const float* four_w1   = (const float*)d_in[8];
    const float* four_w2   = (const float*)d_in[9];
    const float* time_w    = (const float*)d_in[10];
    const float* loc1_w1   = (const float*)d_in[11];
    const float* loc1_b1   = (const float*)d_in[12];
    const float* loc1_w2   = (const float*)d_in[13];
    const float* loc1_b2   = (const float*)d_in[14];
    const float* loc2_w1   = (const float*)d_in[15];
    const float* loc2_b1   = (const float*)d_in[16];
    const float* loc2_w2   = (const float*)d_in[17];
    const float* loc2_b2   = (const float*)d_in[18];
    const float* qkv_w     = (const float*)d_in[19];
    const float* qkv_b     = (const float*)d_in[20];
    const float* out_w     = (const float*)d_in[21];
    const float* out_b     = (const float*)d_in[22];
    const float* ln1_g     = (const float*)d_in[23];
    const float* ln1_b     = (const float*)d_in[24];
    const float* ff1_w     = (const float*)d_in[25];
    const float* ff1_b     = (const float*)d_in[26];
    const float* ff2_w     = (const float*)d_in[27];
    const float* ff2_b     = (const float*)d_in[28];
    const float* gammaW    = (const float*)d_in[29];
    const float* ln2_g     = (const float*)d_in[30];
    const float* ln2_b     = (const float*)d_in[31];

    float *pScale,*pShift,*pEnc,*pLf,*pX,*pSkip,*pBufFF,*pTmp,*pQKV,*pAtt,*pP,*pQ,*pHid,*pOut2,*pZB;
    int *pIdx;
    cudaGetSymbolAddress((void**)&pScale, gScale);
    cudaGetSymbolAddress((void**)&pShift, gShift);
    cudaGetSymbolAddress((void**)&pEnc,   gEnc);
    cudaGetSymbolAddress((void**)&pLf,    gLf);
    cudaGetSymbolAddress((void**)&pX,     gXbuf);
    cudaGetSymbolAddress((void**)&pSkip,  gSkip);
    cudaGetSymbolAddress((void**)&pBufFF, gBufFF);
    cudaGetSymbolAddress((void**)&pTmp,   gTmp);
    cudaGetSymbolAddress((void**)&pQKV,   gQKV);
    cudaGetSymbolAddress((void**)&pAtt,   gAtt);
    cudaGetSymbolAddress((void**)&pP,     gP);
    cudaGetSymbolAddress((void**)&pQ,     gQ);
    cudaGetSymbolAddress((void**)&pHid,   gHid);
    cudaGetSymbolAddress((void**)&pOut2,  gOut2);
    cudaGetSymbolAddress((void**)&pZB,    gZB);
    cudaGetSymbolAddress((void**)&pIdx,   gIdx);

    // KNN-256 needs 132 KB dynamic smem
    int knn2_smem = (128*257 + 128 + 4)*4 + 32;
    cudaFuncSetAttribute(knn_kernel<256>, cudaFuncAttributeMaxDynamicSharedMemorySize, knn2_smem);
    int knn1_smem = (128*2 + 128 + 4)*4 + 32;

    const int EXP_BLOCKS = (ROWS2*128)/256;   // expand kernel: float4 granularity

    // --- time embedding + encoder ---
    time_kernel<<<BB, 256>>>(in_time, four_w1, four_w2, time_w, pScale, pShift);
    enc1_kernel<<<TOK, 512>>>(in_feat, enc_w1, enc_b1, pBufFF);
    gemm_launch(TOK, 256, 512, pBufFF, enc_w2, enc_b2, pEnc, true);
    mod_kernel<<<(TOK*DD)/256, 256>>>(pEnc, in_mask, pScale, pShift);

    // --- local features 1 (KNN in 2D point space, MLP on raw features) ---
    knn_kernel<2><<<BB, 128, knn1_smem>>>(in_pts, in_mask, pIdx);
    locpre1_kernel<<<TOK, 512>>>(in_feat, loc1_w1, loc1_b1, pP, pQ);
    expand_kernel<<<EXP_BLOCKS, 256>>>(pP, pQ, pIdx, pHid);
    gemm_launch(ROWS2, 256, 512, pHid, loc1_w2, loc1_b2, pOut2, true);
    reduce_mean_kernel<<<(TOK*DD)/256, 256>>>(pOut2, nullptr, pLf, nullptr);

    // --- local features 2 (KNN in 256-dim lf space) ---
    knn_kernel<256><<<BB, 128, knn2_smem>>>(pLf, in_mask, pIdx);
    // P2 = lf @ W1[0:256,:]   (zero bias)
    gemm_launch(TOK, 512, 256, pLf, loc2_w1,            pZB,     pP, false);
    // Q2 = lf @ W1[256:512,:] + b1
    gemm_launch(TOK, 512, 256, pLf, loc2_w1 + 256*512,  loc2_b1, pQ, false);
    expand_kernel<<<EXP_BLOCKS, 256>>>(pP, pQ, pIdx, pHid);
    gemm_launch(ROWS2, 256, 512, pHid, loc2_w2, loc2_b2, pOut2, true);
    reduce_mean_kernel<<<(TOK*DD)/256, 256>>>(pOut2, pEnc, pX, pSkip);

    // --- transformer layers ---
    for (int l = 0; l < LL; l++){
        gemm_launch(TOK, 768, 256, pX, qkv_w + (size_t)l*256*768, qkv_b + l*768, pQKV, false);
        attn_kernel<<<BB*HH, 128>>>(pQKV, in_mask, pAtt);
        gemm_launch(TOK, 256, 256, pAtt, out_w + (size_t)l*256*256, out_b + l*256, pTmp, false);
        ln_kernel<<<TOK, 256>>>(pX, pTmp, ln1_g + l*256, ln1_b + l*256, nullptr, in_mask, pX);
        gemm_launch(TOK, 512, 256, pX, ff1_w + (size_t)l*256*512, ff1_b + l*512, pBufFF, true);
        gemm_launch(TOK, 256, 512, pBufFF, ff2_w + (size_t)l*512*256, ff2_b + l*256, pTmp, false);
        ln_kernel<<<TOK, 256>>>(pX, pTmp, ln2_g + l*256, ln2_b + l*256, gammaW + l*256, in_mask, pX);
    }

    // --- final skip add ---
    add_kernel<<<(TOK*DD)/256, 256>>>(pX, pSkip, (float*)d_out);
}

// round 16
// speedup vs baseline: 2.2070x; 1.0012x over previous
#include <cuda_runtime.h>
#include <math.h>
#include <stdint.h>

// ---------------- problem constants ----------------
#define BB   128
#define NN   128
#define FDIM 13
#define DD   256
#define HH   8
#define LL   8
#define KKN  10
#define FFN  512
#define TOK  (BB*NN)       // 16384
#define ROWS2 (TOK*KKN)    // 163840

// ---------------- scratch (device globals; no allocations allowed) ----------
__device__ float gScale[BB*DD];
__device__ float gShift[BB*DD];
__device__ float gEnc [TOK*DD];
__device__ float gLf  [TOK*DD];
__device__ float gXbuf[TOK*DD];
__device__ float gSkip[TOK*DD];
__device__ float gBufFF[TOK*FFN];
__device__ float gTmp [TOK*DD];
__device__ float gQKV [TOK*3*DD];
__device__ float gAtt [TOK*DD];
__device__ float gP   [TOK*FFN];             // per-token top projection
__device__ float gQ   [TOK*FFN];             // per-token bottom projection (+bias)
__device__ float gHid [(size_t)ROWS2*FFN];   // 335 MB
__device__ float gOut2[(size_t)ROWS2*DD];    // 168 MB
__device__ float gZB  [768];                 // zero bias (device globals are zero-init)
__device__ int   gIdx [TOK*KKN];

// ---------------- math helpers ----------------
__device__ __forceinline__ float geluf(float x){
    float x3 = x*x*x;
    return 0.5f*x*(1.f + tanhf(0.7978845608028654f*(x + 0.044715f*x3)));
}
__device__ __forceinline__ float siluf(float x){
    return x / (1.f + expf(-x));
}
__device__ __forceinline__ uint32_t f2tf(float f){
    uint32_t u;
    asm("cvt.rna.tf32.f32 %0, %1;" : "=r"(u) : "f"(f));
    return u;
}
__device__ __forceinline__ float blockReduce256(float v, float* scr){
    #pragma unroll
    for (int o=16;o;o>>=1) v += __shfl_xor_sync(0xffffffffu, v, o);
    if ((threadIdx.x & 31) == 0) scr[threadIdx.x>>5] = v;
    __syncthreads();
    if (threadIdx.x < 32){
        float x = (threadIdx.x < 8) ? scr[threadIdx.x] : 0.f;
        #pragma unroll
        for (int o=4;o;o>>=1) x += __shfl_xor_sync(0xffffffffu, x, o);
        if (threadIdx.x == 0) scr[0] = x;
    }
    __syncthreads();
    float r = scr[0];
    __syncthreads();
    return r;
}

// ---------------- TF32 tensor-core GEMM ----------------
// C = A(MxK) @ B(KxN) + bias, optional GELU.
// Block 128x128, BK=16, 256 threads = 8 warps (2x4), warp tile 64x32.
// mma.sync.aligned.m16n8k8.row.col.f32.tf32.tf32.f32
// Requires M%128==0, N%128==0, K%16==0 (true for all call sites).
#define ASTR 20    // As row stride (floats) — conflict-free fragment loads
#define BSTR 136   // Bs row stride (floats) — conflict-free fragment loads

__device__ __forceinline__ void mma_tf32(float* c, const uint32_t* a,
                                         uint32_t b0, uint32_t b1){
    asm volatile(
        "mma.sync.aligned.m16n8k8.row.col.f32.tf32.tf32.f32 "
        "{%0,%1,%2,%3},{%4,%5,%6,%7},{%8,%9},{%0,%1,%2,%3};"
        : "+f"(c[0]), "+f"(c[1]), "+f"(c[2]), "+f"(c[3])
        : "r"(a[0]), "r"(a[1]), "r"(a[2]), "r"(a[3]), "r"(b0), "r"(b1));
}

template<int EPI>
__global__ void __launch_bounds__(256) tgemm_kernel(int M, int N, int K,
        const float* __restrict__ A, const float* __restrict__ B,
        const float* __restrict__ bias, float* __restrict__ C){
    __shared__ uint32_t As[2][128*ASTR];
    __shared__ uint32_t Bs[2][16*BSTR];
    int tid = threadIdx.x;
    int lane = tid & 31;
    int wid  = tid >> 5;
    int g   = lane >> 2;     // group id 0..7
    int tig = lane & 3;      // thread in group 0..3
    int wm = wid >> 2;       // warp M coord (0..1)
    int wn = wid & 3;        // warp N coord (0..3)
    int br = blockIdx.y, bc = blockIdx.x;
    const float* Ag = A + (size_t)br*128*K;
    const float* Bg = B + (size_t)bc*128;
    float* Cg = C + (size_t)br*128*N + (size_t)bc*128;

    // global-load coordinates (2 float4 each for A and B per thread)
    int aRow0 = tid >> 1;                 // 2 threads per row? no: see below
    (void)aRow0;
    // A tile: 128 rows x 16 cols = 512 float4; idx = tid, tid+256
    // B tile: 16 rows x 128 cols = 512 float4; idx = tid, tid+256

    float acc[4][4][4] = {};

    // ---- fill tile 0 ----
    {
        #pragma unroll
        for (int i=0;i<2;i++){
            int idx = tid + i*256;
            int row = idx >> 2, c4 = (idx & 3) << 2;
            float4 v = *reinterpret_cast<const float4*>(Ag + (size_t)row*K + c4);
            uint32_t* d = &As[0][row*ASTR + c4];
            d[0]=f2tf(v.x); d[1]=f2tf(v.y); d[2]=f2tf(v.z); d[3]=f2tf(v.w);
        }
        #pragma unroll
        for (int i=0;i<2;i++){
            int idx = tid + i*256;
            int row = idx >> 5, c4 = (idx & 31) << 2;
            float4 v = *reinterpret_cast<const float4*>(Bg + (size_t)row*N + c4);
            uint32_t* d = &Bs[0][row*BSTR + c4];
            d[0]=f2tf(v.x); d[1]=f2tf(v.y); d[2]=f2tf(v.z); d[3]=f2tf(v.w);
        }
    }
    __syncthreads();

    int ntiles = K / 16;
    for (int t = 0; t < ntiles; t++){
        int cur = t & 1;
        float4 ap[2], bp[2];
        if (t + 1 < ntiles){
            #pragma unroll
            for (int i=0;i<2;i++){
                int idx = tid + i*256;
                int row = idx >> 2, c4 = (idx & 3) << 2;
                ap[i] = *reinterpret_cast<const float4*>(Ag + (size_t)row*K + (t+1)*16 + c4);
            }
            #pragma unroll
            for (int i=0;i<2;i++){
                int idx = tid + i*256;
                int row = idx >> 5, c4 = (idx & 31) << 2;
                bp[i] = *reinterpret_cast<const float4*>(Bg + (size_t)((t+1)*16 + row)*N + c4);
            }
        }
        // ---- compute on buffer cur: two k-steps of 8 ----
        #pragma unroll
        for (int ks = 0; ks < 2; ks++){
            int k0 = ks * 8;
            uint32_t a[4][4];
            #pragma unroll
            for (int mf = 0; mf < 4; mf++){
                int r0 = (wm*64 + mf*16 + g)*ASTR;
                a[mf][0] = As[cur][r0          + k0 + tig];
                a[mf][1] = As[cur][r0 + 8*ASTR + k0 + tig];
                a[mf][2] = As[cur][r0          + k0 + tig + 4];
                a[mf][3] = As[cur][r0 + 8*ASTR + k0 + tig + 4];
            }
            #pragma unroll
            for (int nf = 0; nf < 4; nf++){
                int cb = wn*32 + nf*8 + g;
                uint32_t b0 = Bs[cur][(k0 + tig    )*BSTR + cb];
                uint32_t b1 = Bs[cur][(k0 + tig + 4)*BSTR + cb];
                #pragma unroll
                for (int mf = 0; mf < 4; mf++)
                    mma_tf32(acc[mf][nf], a[mf], b0, b1);
            }
        }
        if (t + 1 < ntiles){
            int nxt = cur ^ 1;
            #pragma unroll
            for (int i=0;i<2;i++){
                int idx = tid + i*256;
                int row = idx >> 2, c4 = (idx & 3) << 2;
                uint32_t* d = &As[nxt][row*ASTR + c4];
                d[0]=f2tf(ap[i].x); d[1]=f2tf(ap[i].y); d[2]=f2tf(ap[i].z); d[3]=f2tf(ap[i].w);
            }
            #pragma unroll
            for (int i=0;i<2;i++){
                int idx = tid + i*256;
                int row = idx >> 5, c4 = (idx & 31) << 2;
                uint32_t* d = &Bs[nxt][row*BSTR + c4];
                d[0]=f2tf(bp[i].x); d[1]=f2tf(bp[i].y); d[2]=f2tf(bp[i].z); d[3]=f2tf(bp[i].w);
            }
            __syncthreads();
        }
    }

    // ---- epilogue: bias (+ optional GELU), float2 stores ----
    #pragma unroll
    for (int mf = 0; mf < 4; mf++){
        int row0 = wm*64 + mf*16 + g;
        #pragma unroll
        for (int nf = 0; nf < 4; nf++){
            int col = wn*32 + nf*8 + (tig << 1);
            float bx = bias[bc*128 + col];
            float by = bias[bc*128 + col + 1];
            float v0 = acc[mf][nf][0] + bx;
            float v1 = acc[mf][nf][1] + by;
            float v2 = acc[mf][nf][2] + bx;
            float v3 = acc[mf][nf][3] + by;
            if (EPI == 1){
                v0 = geluf(v0); v1 = geluf(v1);
                v2 = geluf(v2); v3 = geluf(v3);
            }
            *reinterpret_cast<float2*>(Cg + (size_t)row0*N + col) = make_float2(v0, v1);
            *reinterpret_cast<float2*>(Cg + (size_t)(row0+8)*N + col) = make_float2(v2, v3);
        }
    }
}

// ---------------- time embedding (per batch) ----------------
__global__ void time_kernel(const float* __restrict__ tin,
        const float* __restrict__ fw1, const float* __restrict__ fw2,
        const float* __restrict__ tw, float* __restrict__ scale,
        float* __restrict__ shift){
    __shared__ float e[256];
    __shared__ float hbuf[512];
    __shared__ float tb[256];
    int b = blockIdx.x, tid = threadIdx.x;  // 256 threads
    float t = tin[b];
    if (tid < 128){
        float emb = 9.210340371976184f / 127.f;   // log(1e4)/(half-1)
        float fr = expf(-emb * (float)tid);
        float ang = t * fr * 1000.f;
        e[tid]      = sinf(ang);
        e[tid+128]  = cosf(ang);
    }
    __syncthreads();
    for (int jj = tid; jj < 512; jj += 256){
        float a = 0.f;
        for (int i=0;i<256;i++) a += e[i]*fw1[i*512+jj];
        hbuf[jj] = siluf(a);
    }
    __syncthreads();
    {
        float a = 0.f;
        for (int i=0;i<512;i++) a += hbuf[i]*fw2[i*256+tid];
        tb[tid] = siluf(a);
    }
    __syncthreads();
    for (int jj = tid; jj < 512; jj += 256){
        float a = 0.f;
        for (int i=0;i<256;i++) a += tb[i]*tw[i*512+jj];
        if (jj < 256) scale[b*256+jj] = a;
        else          shift[b*256+jj-256] = a;
    }
}

// ---------------- encoder layer 1 (K=13, fused gelu) ----------------
__global__ void enc1_kernel(const float* __restrict__ feats,
        const float* __restrict__ w1, const float* __restrict__ b1,
        float* __restrict__ outp){
    __shared__ float f[FDIM];
    int bn = blockIdx.x, j = threadIdx.x; // 512 threads
    if (j < FDIM) f[j] = feats[(size_t)bn*FDIM + j];
    __syncthreads();
    float acc = b1[j];
    #pragma unroll
    for (int i=0;i<FDIM;i++) acc += f[i]*w1[i*512+j];
    outp[(size_t)bn*512 + j] = geluf(acc);
}

// -------- loc1 per-token projections: P = f@W1[0:13], Q = f@W1[13:26] + b1 --
__global__ void locpre1_kernel(const float* __restrict__ feats,
        const float* __restrict__ w1, const float* __restrict__ b1,
        float* __restrict__ P, float* __restrict__ Q){
    __shared__ float f[FDIM];
    int bn = blockIdx.x, j = threadIdx.x; // 512 threads
    if (j < FDIM) f[j] = feats[(size_t)bn*FDIM + j];
    __syncthreads();
    float top = 0.f, bot = 0.f;
    #pragma unroll
    for (int i=0;i<FDIM;i++){
        float fv = f[i];
        top += fv * w1[i*512 + j];
        bot += fv * w1[(FDIM+i)*512 + j];
    }
    P[(size_t)bn*512 + j] = top;
    Q[(size_t)bn*512 + j] = bot + b1[j];
}

// -------- expand: hid[bn,k,j] = gelu(P[nbr] - P[bn] + Q[bn]) ---------------
__global__ void expand_kernel(const float* __restrict__ P,
        const float* __restrict__ Q, const int* __restrict__ idx,
        float* __restrict__ outp){
    int i = blockIdx.x*blockDim.x + threadIdx.x;   // float4 index, < ROWS2*128
    int r = i >> 7;          // row in [0, ROWS2)
    int c4 = (i & 127) << 2; // column base
    int bn = r / KKN;        // token
    int b = bn >> 7;
    int nb = idx[r];         // neighbor index within batch
    const float4 pn = *reinterpret_cast<const float4*>(P + ((size_t)(b*128+nb)*512 + c4));
    const float4 pc = *reinterpret_cast<const float4*>(P + ((size_t)bn*512 + c4));
    const float4 q  = *reinterpret_cast<const float4*>(Q + ((size_t)bn*512 + c4));
    float4 v;
    v.x = geluf(pn.x - pc.x + q.x);
    v.y = geluf(pn.y - pc.y + q.y);
    v.z = geluf(pn.z - pc.z + q.z);
    v.w = geluf(pn.w - pc.w + q.w);
    *reinterpret_cast<float4*>(outp + ((size_t)r*512 + c4)) = v;
}

// ---------------- modulation: enc = enc*(1+m*scale)+m*shift ----------------
__global__ void mod_kernel(float* enc, const float* __restrict__ mask,
        const float* __restrict__ sc, const float* __restrict__ sh){
    int idx = blockIdx.x*blockDim.x + threadIdx.x;
    if (idx >= TOK*DD) return;
    int c = idx & 255, bn = idx >> 8, b = bn >> 7;
    float m = mask[bn];
    enc[idx] = enc[idx]*(1.f + m*sc[b*256+c]) + m*sh[b*256+c];
}

// ---------------- KNN (per batch block, 128 threads, thread=m) --------------
template<int DIM>
__global__ void knn_kernel(const float* __restrict__ pts,
        const float* __restrict__ mask, int* __restrict__ idxout){
    constexpr int P = (DIM == 2) ? 2 : (DIM + 1);
    extern __shared__ float sm[];
    float* qs = sm;                  // 128*P
    float* rs = qs + 128*P;          // 128
    float* wv = rs + 128;            // 4
    int*   wi = (int*)(wv + 4);      // 4
    int*   win = wi + 4;             // 1
    int b = blockIdx.x, tid = threadIdx.x;
    for (int t = tid; t < 128*DIM; t += 128){
        int m = t / DIM, i = t - m*DIM;
        qs[m*P+i] = pts[(size_t)(b*128+m)*DIM + i] + 999.f*(1.f - mask[b*128+m]);
    }
    __syncthreads();
    {
        float s = 0.f;
        for (int i=0;i<DIM;i++){ float v = qs[tid*P+i]; s += v*v; }
        rs[tid] = s;
    }
    __syncthreads();
    for (int n=0;n<128;n++){
        float dot = 0.f;
        for (int i=0;i<DIM;i++) dot += qs[n*P+i]*qs[tid*P+i];
        float myd = (rs[n] - 2.f*dot) + rs[tid];
        for (int rsel=0; rsel<KKN+1; rsel++){
            float v = myd; int ii = tid;
            #pragma unroll
            for (int off=16; off; off>>=1){
                float ov = __shfl_down_sync(0xffffffffu, v, off);
                int   oi = __shfl_down_sync(0xffffffffu, ii, off);
                if (ov < v || (ov == v && oi < ii)){ v = ov; ii = oi; }
            }
            if ((tid & 31) == 0){ wv[tid>>5] = v; wi[tid>>5] = ii; }
            __syncthreads();
            if (tid == 0){
                float bv = wv[0]; int bi = wi[0];
                #pragma unroll
                for (int w=1; w<4; w++)
                    if (wv[w] < bv || (wv[w]==bv && wi[w]<bi)){ bv=wv[w]; bi=wi[w]; }
                *win = bi;
                if (rsel >= 1) idxout[(size_t)(b*128+n)*KKN + (rsel-1)] = bi;
            }
            __syncthreads();
            if (tid == *win) myd = 3.0e38f;
        }
        __syncthreads();
    }
}

// ---------------- mean over K (optionally add enc, dual write) -------------
__global__ void reduce_mean_kernel(const float* __restrict__ in,
        const float* __restrict__ addsrc, float* __restrict__ out,
        float* __restrict__ out2){
    int idx = blockIdx.x*blockDim.x + threadIdx.x;
    if (idx >= TOK*DD) return;
    int bn = idx >> 8, c = idx & 255;
    const float* p = in + ((size_t)bn*KKN)*256 + c;
    float s = 0.f;
    #pragma unroll
    for (int k=0;k<KKN;k++) s += p[(size_t)k*256];
    s *= (1.f/KKN);
    if (addsrc){
        float v = addsrc[idx] + s;
        out[idx] = v;
        out2[idx] = v;
    } else {
        out[idx] = s;
    }
}

// ---------------- attention (per (b,h) block; two-pass softmax) -------------
__global__ void __launch_bounds__(128) attn_kernel(const float* __restrict__ qkv,
        const float* __restrict__ mask, float* __restrict__ outp){
    __shared__ float Ks[128*32];
    __shared__ float Vs[128*32];
    __shared__ float Ms[128];
    int b = blockIdx.x >> 3, h = blockIdx.x & 7;
    int tid = threadIdx.x; // 128
    const float* base = qkv + (size_t)b*128*768;
    for (int t = tid; t < 128*8; t += 128){
        int m = t >> 3, dq = (t & 7) << 2;
        *reinterpret_cast<float4*>(&Ks[m*32+dq]) =
            *reinterpret_cast<const float4*>(&base[(size_t)m*768 + 256 + h*32 + dq]);
        *reinterpret_cast<float4*>(&Vs[m*32+dq]) =
            *reinterpret_cast<const float4*>(&base[(size_t)m*768 + 512 + h*32 + dq]);
    }
    Ms[tid] = mask[b*128+tid];
    float q[32];
    #pragma unroll
    for (int d=0; d<32; d+=4)
        *reinterpret_cast<float4*>(&q[d]) =
            *reinterpret_cast<const float4*>(&base[(size_t)tid*768 + h*32 + d]);
    __syncthreads();
    const float scl = 0.17677669529663687f; // 1/sqrt(32)
    float mx = -1e30f;
    for (int m=0;m<128;m++){
        float s = 0.f;
        #pragma unroll
        for (int d=0; d<32; d++) s += q[d]*Ks[m*32+d];
        s = (Ms[m] > 0.f) ? s*scl : -1e9f;
        mx = fmaxf(mx, s);
    }
    float sum = 0.f;
    float acc[32] = {};
    for (int m=0;m<128;m++){
        float s = 0.f;
        #pragma unroll
        for (int d=0; d<32; d++) s += q[d]*Ks[m*32+d];
        s = (Ms[m] > 0.f) ? s*scl : -1e9f;
        float e = expf(s - mx);
        sum += e;
        #pragma unroll
        for (int d=0; d<32; d++) acc[d] += e*Vs[m*32+d];
    }
    float inv = 1.f/sum;
    float* o = outp + (size_t)(b*128+tid)*256 + h*32;
    #pragma unroll
    for (int d=0; d<32; d+=4){
        float4 v; v.x=acc[d]*inv; v.y=acc[d+1]*inv; v.z=acc[d+2]*inv; v.w=acc[d+3]*inv;
        *reinterpret_cast<float4*>(o + d) = v;
    }
}

// ---------------- residual + LayerNorm (optional gamma*mask on t) -----------
__global__ void ln_kernel(const float* res, const float* t,
        const float* __restrict__ g, const float* __restrict__ bb,
        const float* __restrict__ gamma, const float* __restrict__ mask,
        float* outp){
    __shared__ float scr[8];
    int bn = blockIdx.x, c = threadIdx.x; // 256 threads
    size_t off = (size_t)bn*256 + c;
    float hv = t[off];
    if (gamma) hv *= gamma[c] * mask[bn];
    float v = res[off] + hv;
    float mean = blockReduce256(v, scr) * (1.f/256.f);
    float d = v - mean;
    float var = blockReduce256(d*d, scr) * (1.f/256.f);
    outp[off] = d * rsqrtf(var + 1e-5f) * g[c] + bb[c];
}

// ---------------- final add ----------------
__global__ void add_kernel(const float* __restrict__ a, const float* __restrict__ b,
        float* __restrict__ o){
    int idx = blockIdx.x*blockDim.x + threadIdx.x;
    if (idx >= TOK*DD) return;
    o[idx] = a[idx] + b[idx];
}

// ---------------- host ----------------
static void gemm_launch(int M, int N, int K, const float* A, const float* B,
                        const float* bias, float* C, bool ge){
    dim3 grid(N/128, M/128);
    if (ge) tgemm_kernel<1><<<grid, 256>>>(M, N, K, A, B, bias, C);
    else    tgemm_kernel<0><<<grid, 256>>>(M, N, K, A, B, bias, C);
}

extern "C" void kernel_launch(void* const* d_in, const int* in_sizes, int n_in,
                              void* d_out, int out_size){
    const float* in_feat   = (const float*)d_in[0];
    const float* in_pts    = (const float*)d_in[1];
    const float* in_mask   = (const float*)d_in[2];
    const float* in_time   = (const float*)d_in[3];
    const float* enc_w1    = (const float*)d_in[4];
    const float* enc_b1    = (const float*)d_in[5];
    const float* enc_w2    = (const float*)d_in[6];
    const float* enc_b2    = (const float*)d_in[7];
    const float* four_w1   = (const float*)d_in[8];
    const float* four_w2   = (const float*)d_in[9];
    const float* time_w    = (const float*)d_in[10];
    const float* loc1_w1   = (const float*)d_in[11];
    const float* loc1_b1   = (const float*)d_in[12];
    const float* loc1_w2   = (const float*)d_in[13];
    const float* loc1_b2   = (const float*)d_in[14];
    const float* loc2_w1   = (const float*)d_in[15];
    const float* loc2_b1   = (const float*)d_in[16];
    const float* loc2_w2   = (const float*)d_in[17];
    const float* loc2_b2   = (const float*)d_in[18];
    const float* qkv_w     = (const float*)d_in[19];
    const float* qkv_b     = (const float*)d_in[20];
    const float* out_w     = (const float*)d_in[21];
    const float* out_b     = (const float*)d_in[22];
    const float* ln1_g     = (const float*)d_in[23];
    const float* ln1_b     = (const float*)d_in[24];
    const float* ff1_w     = (const float*)d_in[25];
    const float* ff1_b     = (const float*)d_in[26];
    const float* ff2_w     = (const float*)d_in[27];
    const float* ff2_b     = (const float*)d_in[28];
    const float* gammaW    = (const float*)d_in[29];
    const float* ln2_g     = (const float*)d_in[30];
    const float* ln2_b     = (const float*)d_in[31];

    float *pScale,*pShift,*pEnc,*pLf,*pX,*pSkip,*pBufFF,*pTmp,*pQKV,*pAtt,*pP,*pQ,*pHid,*pOut2,*pZB;
    int *pIdx;
    cudaGetSymbolAddress((void**)&pScale, gScale);
    cudaGetSymbolAddress((void**)&pShift, gShift);
    cudaGetSymbolAddress((void**)&pEnc,   gEnc);
    cudaGetSymbolAddress((void**)&pLf,    gLf);
    cudaGetSymbolAddress((void**)&pX,     gXbuf);
    cudaGetSymbolAddress((void**)&pSkip,  gSkip);
    cudaGetSymbolAddress((void**)&pBufFF, gBufFF);
    cudaGetSymbolAddress((void**)&pTmp,   gTmp);
    cudaGetSymbolAddress((void**)&pQKV,   gQKV);
    cudaGetSymbolAddress((void**)&pAtt,   gAtt);
    cudaGetSymbolAddress((void**)&pP,     gP);
    cudaGetSymbolAddress((void**)&pQ,     gQ);
    cudaGetSymbolAddress((void**)&pHid,   gHid);
    cudaGetSymbolAddress((void**)&pOut2,  gOut2);
    cudaGetSymbolAddress((void**)&pZB,    gZB);
    cudaGetSymbolAddress((void**)&pIdx,   gIdx);

    // KNN-256 needs 132 KB dynamic smem
    int knn2_smem = (128*257 + 128 + 4)*4 + 32;
    cudaFuncSetAttribute(knn_kernel<256>, cudaFuncAttributeMaxDynamicSharedMemorySize, knn2_smem);
    int knn1_smem = (128*2 + 128 + 4)*4 + 32;

    const int EXP_BLOCKS = (ROWS2*128)/256;   // expand kernel: float4 granularity

    // --- time embedding + encoder ---
    time_kernel<<<BB, 256>>>(in_time, four_w1, four_w2, time_w, pScale, pShift);
    enc1_kernel<<<TOK, 512>>>(in_feat, enc_w1, enc_b1, pBufFF);
    gemm_launch(TOK, 256, 512, pBufFF, enc_w2, enc_b2, pEnc, true);
    mod_kernel<<<(TOK*DD)/256, 256>>>(pEnc, in_mask, pScale, pShift);

    // --- local features 1 (KNN in 2D point space, MLP on raw features) ---
    knn_kernel<2><<<BB, 128, knn1_smem>>>(in_pts, in_mask, pIdx);
    locpre1_kernel<<<TOK, 512>>>(in_feat, loc1_w1, loc1_b1, pP, pQ);
    expand_kernel<<<EXP_BLOCKS, 256>>>(pP, pQ, pIdx, pHid);
    gemm_launch(ROWS2, 256, 512, pHid, loc1_w2, loc1_b2, pOut2, true);
    reduce_mean_kernel<<<(TOK*DD)/256, 256>>>(pOut2, nullptr, pLf, nullptr);

    // --- local features 2 (KNN in 256-dim lf space) ---
    knn_kernel<256><<<BB, 128, knn2_smem>>>(pLf, in_mask, pIdx);
    // P2 = lf @ W1[0:256,:]   (zero bias)
    gemm_launch(TOK, 512, 256, pLf, loc2_w1,            pZB,     pP, false);
    // Q2 = lf @ W1[256:512,:] + b1
    gemm_launch(TOK, 512, 256, pLf, loc2_w1 + 256*512,  loc2_b1, pQ, false);
    expand_kernel<<<EXP_BLOCKS, 256>>>(pP, pQ, pIdx, pHid);
    gemm_launch(ROWS2, 256, 512, pHid, loc2_w2, loc2_b2, pOut2, true);
    reduce_mean_kernel<<<(TOK*DD)/256, 256>>>(pOut2, pEnc, pX, pSkip);

    // --- transformer layers ---
    for (int l = 0; l < LL; l++){
        gemm_launch(TOK, 768, 256, pX, qkv_w + (size_t)l*256*768, qkv_b + l*768, pQKV, false);
        attn_kernel<<<BB*HH, 128>>>(pQKV, in_mask, pAtt);
        gemm_launch(TOK, 256, 256, pAtt, out_w + (size_t)l*256*256, out_b + l*256, pTmp, false);
        ln_kernel<<<TOK, 256>>>(pX, pTmp, ln1_g + l*256, ln1_b + l*256, nullptr, in_mask, pX);
        gemm_launch(TOK, 512, 256, pX, ff1_w + (size_t)l*256*512, ff1_b + l*512, pBufFF, true);
        gemm_launch(TOK, 256, 512, pBufFF, ff2_w + (size_t)l*512*256, ff2_b + l*256, pTmp, false);
        ln_kernel<<<TOK, 256>>>(pX, pTmp, ln2_g + l*256, ln2_b + l*256, gammaW + l*256, in_mask, pX);
    }

    // --- final skip add ---
    add_kernel<<<(TOK*DD)/256, 256>>>(pX, pSkip, (float*)d_out);
}